// round 14
// baseline (speedup 1.0000x reference)
#include <cuda_runtime.h>
#include <cuda_fp16.h>
#include <cstdint>

#define BATCH 4
#define LSEQ  2048
#define DDIM  256
#define HDIM  512
#define WBAND 128
#define NSPLIT 4
#define L3D   (3*DDIM)
#define NEXT  (L3D + HDIM)   // 1280 packed output cols
#define BANDBACK 96

#define S_LD  ((long)LSEQ*DDIM)
#define S_LH  ((long)LSEQ*HDIM)
#define S_LL  ((long)LSEQ*LSEQ)
#define S_HD  ((long)HDIM*DDIM)
#define S_DH  ((long)DDIM*HDIM)
#define S_L3D ((long)LSEQ*L3D)

// ---------------- scratch ----------------
__device__ __half g_xh   [BATCH*LSEQ*DDIM];
__device__ __half g_WqkvT[3*DDIM*DDIM];
__device__ __half g_Mh   [BATCH*HDIM*DDIM];     // folded Wk@W1^T, [h][d]
__device__ float  g_bqkv [3*DDIM];
__device__ float  g_b1add[BATCH*HDIM];
__device__ __half g_W1h  [BATCH*HDIM*DDIM];
__device__ __half g_W2h  [BATCH*DDIM*HDIM];
__device__ __half g_W2Th [BATCH*HDIM*DDIM];
__device__ float  g_qkvf [BATCH*LSEQ*L3D];
__device__ __half g_qkvh [BATCH*LSEQ*L3D];
__device__ __half g_Z1h  [BATCH*LSEQ*HDIM];
__device__ __half g_X2h  [BATCH*LSEQ*HDIM];
__device__ __half g_gZ2h [BATCH*LSEQ*DDIM];
__device__ __half g_gZ1h [BATCH*LSEQ*HDIM];
__device__ __half g_X2nh [BATCH*LSEQ*HDIM];
__device__ __half g_Sh   [(size_t)BATCH*LSEQ*LSEQ];
__device__ float  g_Wsp1 [BATCH*NSPLIT*HDIM*DDIM];
__device__ float  g_Wsp2 [BATCH*NSPLIT*DDIM*HDIM];
__device__ float  g_lr   [BATCH*LSEQ];
__device__ double g_LcD  [BATCH*LSEQ];
__device__ float  g_cexp [BATCH*LSEQ];
__device__ float  g_wfac [BATCH*LSEQ];
__device__ float  g_clast[BATCH];
__device__ float  g_lrraw[BATCH*LSEQ];
__device__ float  g_wdraw[BATCH*LSEQ];

// ---------------- helpers ----------------
__device__ __forceinline__ uint32_t smem_u32(const void* p) {
    return (uint32_t)__cvta_generic_to_shared(p);
}
__device__ __forceinline__ float sigf(float x) {
    return __fdividef(1.0f, 1.0f + __expf(-x));
}
__device__ __forceinline__ void cpasync16(uint32_t dst, const void* src) {
    asm volatile("cp.async.cg.shared.global [%0], [%1], 16;\n" :: "r"(dst), "l"(src));
}
__device__ __forceinline__ void cp_commit() { asm volatile("cp.async.commit_group;\n" ::: "memory"); }
__device__ __forceinline__ void cp_wait1()  { asm volatile("cp.async.wait_group 1;\n" ::: "memory"); }
__device__ __forceinline__ void cp_wait0()  { asm volatile("cp.async.wait_group 0;\n" ::: "memory"); }
__device__ __forceinline__ void ldsm4(uint32_t& r0, uint32_t& r1, uint32_t& r2, uint32_t& r3, uint32_t a) {
    asm volatile("ldmatrix.sync.aligned.m8n8.x4.shared.b16 {%0,%1,%2,%3}, [%4];\n"
                 : "=r"(r0), "=r"(r1), "=r"(r2), "=r"(r3) : "r"(a));
}
__device__ __forceinline__ void ldsm4t(uint32_t& r0, uint32_t& r1, uint32_t& r2, uint32_t& r3, uint32_t a) {
    asm volatile("ldmatrix.sync.aligned.m8n8.x4.trans.shared.b16 {%0,%1,%2,%3}, [%4];\n"
                 : "=r"(r0), "=r"(r1), "=r"(r2), "=r"(r3) : "r"(a));
}
__device__ __forceinline__ void mma16816(float* d, const uint32_t* a, uint32_t b0, uint32_t b1) {
    asm volatile("mma.sync.aligned.m16n8k16.row.col.f32.f16.f16.f32 "
                 "{%0,%1,%2,%3}, {%4,%5,%6,%7}, {%8,%9}, {%0,%1,%2,%3};\n"
                 : "+f"(d[0]), "+f"(d[1]), "+f"(d[2]), "+f"(d[3])
                 : "r"(a[0]), "r"(a[1]), "r"(a[2]), "r"(a[3]), "r"(b0), "r"(b1));
}

#define SLOT     20480
#define SMEM_DYN (3 * SLOT)

// stage loaders
__device__ __forceinline__ void ld_mk(uint32_t dst, const __half* src, int ld, int r0, int k0, int tid) {
#pragma unroll
    for (int i = 0; i < 2; i++) {
        int c = i * 256 + tid, row = c >> 2, ch = c & 3;
        cpasync16(dst + row * 80 + ch * 16, src + (long)(r0 + row) * ld + k0 + ch * 8);
    }
}
__device__ __forceinline__ void ld_kn(uint32_t dst, const __half* src, int ld, int n0, int k0, int tid) {
#pragma unroll
    for (int i = 0; i < 2; i++) {
        int c = i * 256 + tid, k = c >> 4, ch = c & 15;
        cpasync16(dst + k * 272 + ch * 16, src + (long)(k0 + k) * ld + n0 + ch * 8);
    }
}
__device__ __forceinline__ void st_km_scaled(char* slotp, const __half* A, int lda, int m0, int k0,
                                             const float* wsc, int tid) {
    __half* smA = (__half*)slotp;
#pragma unroll
    for (int i = 0; i < 16; i++) {
        int e = i * 256 + tid, k = e >> 7, m = e & 127;
        smA[k * 136 + m] = __float2half_rn(__half2float(A[(long)(k0 + k) * lda + m0 + m]) * wsc[k0 + k]);
    }
}

// ---------------- fragment loaders ----------------
template<int TB>
__device__ __forceinline__ void ldB_frag(uint32_t bb, int ks, uint32_t (&Bp)[4][2], int lane, int wn) {
#pragma unroll
    for (int nj = 0; nj < 2; nj++) {
        uint32_t r0, r1, r2, r3;
        if (TB == 1) {
            uint32_t addr = bb + (uint32_t)((wn * 32 + nj * 16 + (lane & 15)) * 80
                                            + (ks * 16 + (lane >> 4) * 8) * 2);
            ldsm4(r0, r1, r2, r3, addr);
            Bp[nj*2][0] = r0; Bp[nj*2][1] = r2; Bp[nj*2+1][0] = r1; Bp[nj*2+1][1] = r3;
        } else {
            uint32_t addr = bb + (uint32_t)((ks * 16 + (lane & 15)) * 272
                                            + (wn * 32 + nj * 16 + (lane >> 4) * 8) * 2);
            ldsm4t(r0, r1, r2, r3, addr);
            Bp[nj*2][0] = r0; Bp[nj*2][1] = r1; Bp[nj*2+1][0] = r2; Bp[nj*2+1][1] = r3;
        }
    }
}
template<int TA>
__device__ __forceinline__ void ldA_frag(uint32_t ab, int ks, int mi, uint32_t (&Af)[4], int lane, int wm) {
    if (TA == 0) {
        uint32_t addr = ab + (uint32_t)((wm * 64 + mi * 16 + (lane & 15)) * 80
                                        + (ks * 16 + (lane >> 4) * 8) * 2);
        ldsm4(Af[0], Af[1], Af[2], Af[3], addr);
    } else {
        uint32_t addr = ab + (uint32_t)((ks * 16 + (lane & 7) + ((lane >> 4) << 3)) * 272
                                        + (wm * 64 + mi * 16 + ((lane >> 3) & 1) * 8) * 2);
        ldsm4t(Af[0], Af[1], Af[2], Af[3], addr);
    }
}

template<int TA, int TB>
__device__ __forceinline__ void compute_tile(uint32_t ab, uint32_t bb,
                                             float (&acc)[4][4][4], int lane, int wm, int wn)
{
    uint32_t Bp[2][4][2];
    uint32_t Af[2][4];
    ldB_frag<TB>(bb, 0, Bp[0], lane, wn);
    ldA_frag<TA>(ab, 0, 0, Af[0], lane, wm);
    ldB_frag<TB>(bb, 1, Bp[1], lane, wn);
#pragma unroll
    for (int ks = 0; ks < 2; ks++) {
#pragma unroll
        for (int mi = 0; mi < 4; mi++) {
            if (mi < 3)       ldA_frag<TA>(ab, ks, mi + 1, Af[(mi + 1) & 1], lane, wm);
            else if (ks == 0) ldA_frag<TA>(ab, 1, 0,      Af[0],            lane, wm);
#pragma unroll
            for (int ni = 0; ni < 4; ni++)
                mma16816(acc[mi][ni], Af[mi & 1], Bp[ks][ni][0], Bp[ks][ni][1]);
        }
    }
}

// full mainloop
template<int TB>
__device__ __forceinline__ void gemm_loop(uint32_t sb,
                                          const __half* A, int lda, int m0,
                                          const __half* B, int ldb, int n0,
                                          int kbeg, int kend, float (&acc)[4][4][4],
                                          int tid, int lane, int wm, int wn)
{
    const int nkt = (kend - kbeg) >> 5;
    ld_mk(sb, A, lda, m0, kbeg, tid);
    if (TB == 1) ld_mk(sb + 10240, B, ldb, n0, kbeg, tid);
    else         ld_kn(sb + 10240, B, ldb, n0, kbeg, tid);
    cp_commit();
    if (nkt > 1) {
        ld_mk(sb + SLOT, A, lda, m0, kbeg + 32, tid);
        if (TB == 1) ld_mk(sb + SLOT + 10240, B, ldb, n0, kbeg + 32, tid);
        else         ld_kn(sb + SLOT + 10240, B, ldb, n0, kbeg + 32, tid);
    }
    cp_commit();
    for (int kt = 0; kt < nkt; kt++) {
        cp_wait1(); __syncthreads();
        if (kt + 2 < nkt) {
            int sl = (kt + 2) % 3;
            int k0 = kbeg + (kt + 2) * 32;
            ld_mk(sb + sl * SLOT, A, lda, m0, k0, tid);
            if (TB == 1) ld_mk(sb + sl * SLOT + 10240, B, ldb, n0, k0, tid);
            else         ld_kn(sb + sl * SLOT + 10240, B, ldb, n0, k0, tid);
        }
        cp_commit();
        uint32_t ab = sb + (uint32_t)(kt % 3) * SLOT;
        compute_tile<0, TB>(ab, ab + 10240, acc, lane, wm, wn);
    }
}

// negated masked-decay S epilogue
__device__ __forceinline__ void s_epilogue(float (&acc)[4][4][4], __half* ShB,
                                           int m0, int n0,
                                           const float* lrv, const double* LcD,
                                           float* sFr, float* sFc,
                                           int tid, int lane, int wm, int wn)
{
    const int g = lane >> 2, t4 = lane & 3;
    if (tid < 128) sFr[tid] = __expf((float)(LcD[m0 + tid] - LcD[m0]));
    else { int i = tid - 128; sFc[i] = __expf((float)(LcD[m0] - LcD[n0 + i])) * lrv[n0 + i]; }
    __syncthreads();
#pragma unroll
    for (int mi = 0; mi < 4; mi++)
#pragma unroll
    for (int hf = 0; hf < 2; hf++) {
        const int r = m0 + wm * 64 + mi * 16 + g + hf * 8;
        const float f1 = sFr[r - m0];
#pragma unroll
        for (int ni = 0; ni < 4; ni++) {
            const int cc = n0 + wn * 32 + ni * 8 + t4 * 2;
            const int cl = wn * 32 + ni * 8 + t4 * 2;
            float v0 = acc[mi][ni][hf * 2], v1 = acc[mi][ni][hf * 2 + 1];
            float o0 = (cc     <= r) ? -(v0 * f1 * sFc[cl])     : 0.f;
            float o1 = (cc + 1 <= r) ? -(v1 * f1 * sFc[cl + 1]) : 0.f;
            *(__half2*)&ShB[(long)r * LSEQ + cc] = __floats2half2_rn(o0, o1);
        }
    }
}

// ---------------- extended QKV+Z1 GEMM (N=1280) + scan merged ----------------
__global__ void __launch_bounds__(256, 2) qkvext_k(
    const __half* __restrict__ xh, const __half* __restrict__ WqkvT,
    const __half* __restrict__ Mh,
    float* __restrict__ qkvf, __half* __restrict__ qkvh,
    __half* __restrict__ Z1h, __half* __restrict__ X2h,
    const float* __restrict__ bqkv, const float* __restrict__ b1add,
    const float* __restrict__ lrraw, const float* __restrict__ wdraw,
    const float* __restrict__ lbl, const float* __restrict__ lbw,
    float* __restrict__ lr, double* __restrict__ LcD,
    float* __restrict__ cexp, float* __restrict__ wfac,
    float* __restrict__ clast)
{
    const int tid = threadIdx.x;
    if (blockIdx.x == 10) {
        if (blockIdx.y != 0) return;
        const int b = blockIdx.z;
        __shared__ double ssum[256];
        __shared__ double sLast;
        const float ewd = expf(lbw[0]);
        const float elr = expf(lbl[0]);
        double loc[8];
        double tot = 0.0;
        const int base = b * LSEQ + tid * 8;
#pragma unroll
        for (int i = 0; i < 8; i++) {
            float sig = 1.f / (1.f + expf(-wdraw[base + i]));
            double lw = log(1.0 - (double)ewd * (double)sig);
            tot += lw;
            loc[i] = tot;
        }
        ssum[tid] = tot;
        __syncthreads();
        for (int off = 1; off < 256; off <<= 1) {
            double v = (tid >= off) ? ssum[tid - off] : 0.0;
            __syncthreads();
            ssum[tid] += v;
            __syncthreads();
        }
        double excl = (tid == 0) ? 0.0 : ssum[tid - 1];
        if (tid == 255) sLast = ssum[255];
        __syncthreads();
        double last = sLast;
#pragma unroll
        for (int i = 0; i < 8; i++) {
            double Lc = excl + loc[i];
            LcD[base + i] = Lc;
            cexp[base + i] = (float)exp(Lc);
            float l_r = elr / (1.f + expf(-lrraw[base + i]));
            lr[base + i] = l_r;
            wfac[base + i] = (float)((double)l_r * exp(last - Lc));
        }
        if (tid == 0) clast[b] = (float)exp(last);
        return;
    }

    const int bz = blockIdx.z;
    const int m0 = blockIdx.y * 128, n0 = blockIdx.x * 128;
    const __half* A = xh + bz * S_LD;
    const __half* B;
    int n0e;
    if (n0 < 768) { B = WqkvT;              n0e = n0; }
    else          { B = Mh + bz * S_HD;     n0e = n0 - 768; }

    extern __shared__ __align__(16) char dynsm[];
    const uint32_t sb = smem_u32(dynsm);
    const int w = tid >> 5, lane = tid & 31;
    const int wm = w >> 2, wn = w & 3, g = lane >> 2, t4 = lane & 3;

    float acc[4][4][4] = {};
    gemm_loop<1>(sb, A, DDIM, m0, B, DDIM, n0e, 0, DDIM, acc, tid, lane, wm, wn);

    float*  Vf  = qkvf + bz * S_L3D;
    __half* QKh = qkvh + bz * S_L3D;
    __half* Z1b = Z1h + bz * S_LH;
    __half* X2b = X2h + bz * S_LH;
    const float* b1b = b1add + (long)bz * HDIM;

#pragma unroll
    for (int mi = 0; mi < 4; mi++)
#pragma unroll
    for (int hf = 0; hf < 2; hf++) {
        const int r = m0 + wm * 64 + mi * 16 + g + hf * 8;
#pragma unroll
        for (int ni = 0; ni < 4; ni++) {
            const int cc = n0 + wn * 32 + ni * 8 + t4 * 2;
            float v0 = acc[mi][ni][hf * 2 + 0], v1 = acc[mi][ni][hf * 2 + 1];
            if (cc < 512) {
                float o0 = v0 + bqkv[cc], o1 = v1 + bqkv[cc + 1];
                *(__half2*)&QKh[(long)r * L3D + cc] = __floats2half2_rn(o0, o1);
            } else if (cc < 768) {
                float o0 = v0 + bqkv[cc], o1 = v1 + bqkv[cc + 1];
                *(float2*)&Vf[(long)r * L3D + cc] = make_float2(o0, o1);
            } else {
                const int h = cc - 768;
                float z0 = v0 + b1b[h], z1 = v1 + b1b[h + 1];
                *(__half2*)&Z1b[(long)r * HDIM + h] = __floats2half2_rn(z0, z1);
                *(__half2*)&X2b[(long)r * HDIM + h] =
                    __floats2half2_rn(z0 * sigf(z0), z1 * sigf(z1));
            }
        }
    }
}

// ---------------- gZ1 GEMM ----------------
__global__ void __launch_bounds__(256, 2) gz1_k(
    const __half* __restrict__ A, long sA, int lda,
    const __half* __restrict__ B, long sB, int ldb,
    __half* __restrict__ C, long sC, int ldc, int K,
    const __half* __restrict__ aux, long sAux, int ldaux)
{
    const int bz = blockIdx.z;
    const int m0 = blockIdx.y * 128, n0 = blockIdx.x * 128;
    A += bz * sA; B += bz * sB;
    C += bz * sC;
    aux += bz * sAux;

    extern __shared__ __align__(16) char dynsm[];
    const uint32_t sb = smem_u32(dynsm);
    const int tid = threadIdx.x, w = tid >> 5, lane = tid & 31;
    const int wm = w >> 2, wn = w & 3, g = lane >> 2, t4 = lane & 3;

    float acc[4][4][4] = {};
    gemm_loop<1>(sb, A, lda, m0, B, ldb, n0, 0, K, acc, tid, lane, wm, wn);

#pragma unroll
    for (int mi = 0; mi < 4; mi++)
#pragma unroll
    for (int hf = 0; hf < 2; hf++) {
        const int r = m0 + wm * 64 + mi * 16 + g + hf * 8;
#pragma unroll
        for (int ni = 0; ni < 4; ni++) {
            const int cc = n0 + wn * 32 + ni * 8 + t4 * 2;
            float v0 = acc[mi][ni][hf * 2 + 0], v1 = acc[mi][ni][hf * 2 + 1];
            __half2 a2 = *(const __half2*)&aux[(long)r * ldaux + cc];
            float ax = __half2float(__low2half(a2));
            float ay = __half2float(__high2half(a2));
            float s0 = sigf(ax), s1 = sigf(ay);
            float i0 = ax * s0, i1 = ay * s1;
            *(__half2*)&C[(long)r * ldc + cc] = __floats2half2_rn(
                (i0 + s0 * (1.f - i0)) * v0, (i1 + s1 * (1.f - i1)) * v1);
        }
    }
}

// ---------------- gZ2 (32 tiles) + S1-gen (31 tiles) merged per batch ----------------
__global__ void __launch_bounds__(256, 2) gzs1_k(
    const __half* __restrict__ X2h, const __half* __restrict__ W2h,
    const float* __restrict__ qkvf, __half* __restrict__ gZ2h,
    const __half* __restrict__ qkvh, __half* __restrict__ Sh,
    const float* __restrict__ lrv, const double* __restrict__ LcD)
{
    const int bz = blockIdx.z;
    const int t = blockIdx.x;
    extern __shared__ __align__(16) char dynsm[];
    const uint32_t sb = smem_u32(dynsm);
    __shared__ float sFr[128], sFc[128];
    const int tid = threadIdx.x, w = tid >> 5, lane = tid & 31;
    const int wm = w >> 2, wn = w & 3, g = lane >> 2, t4 = lane & 3;
    float acc[4][4][4] = {};

    if (t < 32) {
        const int m0 = (t >> 1) * 128, n0 = (t & 1) * 128;
        gemm_loop<1>(sb, X2h + bz * S_LH, HDIM, m0, W2h + bz * S_DH, HDIM, n0,
                     0, HDIM, acc, tid, lane, wm, wn);
        const float* Vf = qkvf + bz * S_L3D + 2 * DDIM;
        __half* C = gZ2h + bz * S_LD;
#pragma unroll
        for (int mi = 0; mi < 4; mi++)
#pragma unroll
        for (int hf = 0; hf < 2; hf++) {
            const int r = m0 + wm * 64 + mi * 16 + g + hf * 8;
#pragma unroll
            for (int ni = 0; ni < 4; ni++) {
                const int cc = n0 + wn * 32 + ni * 8 + t4 * 2;
                float2 a = *(const float2*)&Vf[(long)r * L3D + cc];
                *(__half2*)&C[(long)r * DDIM + cc] = __floats2half2_rn(
                    acc[mi][ni][hf * 2] - a.x, acc[mi][ni][hf * 2 + 1] - a.y);
            }
        }
        return;
    }
    const int tt = t - 32;
    const int mm = (tt < 16) ? tt : tt - 15;
    const int nn = (tt < 16) ? tt : tt - 16;
    const int m0 = mm * 128, n0 = nn * 128;
    gemm_loop<1>(sb, qkvh + bz * S_L3D, L3D, m0, qkvh + bz * S_L3D + DDIM, L3D, n0,
                 0, DDIM, acc, tid, lane, wm, wn);
    s_epilogue(acc, Sh + bz * S_LL, m0, n0,
               lrv + (long)bz * LSEQ, LcD + (long)bz * LSEQ, sFr, sFc, tid, lane, wm, wn);
}

// ---------------- attn1 (fused cross+band) + W1/W2-next partials merged ----------------
__global__ void __launch_bounds__(256, 2) attn1wp_k(
    const __half* __restrict__ qkvh, const __half* __restrict__ W1h,
    const __half* __restrict__ Sh, const __half* __restrict__ gZ1h,
    __half* __restrict__ X2nh, const float* __restrict__ cexp,
    const __half* __restrict__ gZ2h, const __half* __restrict__ X2h,
    float* __restrict__ Wsp1, float* __restrict__ Wsp2,
    const float* __restrict__ wfac)
{
    extern __shared__ __align__(16) char dynsm[];
    const uint32_t sb = smem_u32(dynsm);
    const int tid = threadIdx.x, w = tid >> 5, lane = tid & 31;
    const int wm = w >> 2, wn = w & 3, g = lane >> 2, t4 = lane & 3;
    float acc[4][4][4] = {};
    const int x = blockIdx.x;

    if (x < 256) {
        const int bz = x >> 6, rem = x & 63;
        const int m0 = (rem >> 2) * 128, n0 = (rem & 3) * 128;
        const __half* Q = qkvh + bz * S_L3D;
        const float* ce = cexp + (long)bz * LSEQ;
        if (ce[m0] >= 1e-30f) {
            gemm_loop<1>(sb, Q, L3D, m0, W1h + bz * S_HD, DDIM, n0,
                         0, DDIM, acc, tid, lane, wm, wn);
#pragma unroll
            for (int mi = 0; mi < 4; mi++)
#pragma unroll
            for (int hf = 0; hf < 2; hf++) {
                const float s = ce[m0 + wm * 64 + mi * 16 + g + hf * 8];
#pragma unroll
                for (int ni = 0; ni < 4; ni++) {
                    acc[mi][ni][hf * 2 + 0] *= s;
                    acc[mi][ni][hf * 2 + 1] *= s;
                }
            }
            cp_wait0(); __syncthreads();
        }
        const int kbeg = (m0 >= 128) ? m0 - BANDBACK : 0;
        gemm_loop<0>(sb, Sh + bz * S_LL, LSEQ, m0, gZ1h + bz * S_LH, HDIM, n0,
                     kbeg, m0 + 128, acc, tid, lane, wm, wn);
        __half* C = X2nh + bz * S_LH;
#pragma unroll
        for (int mi = 0; mi < 4; mi++)
#pragma unroll
        for (int hf = 0; hf < 2; hf++) {
            const int r = m0 + wm * 64 + mi * 16 + g + hf * 8;
#pragma unroll
            for (int ni = 0; ni < 4; ni++) {
                const int cc = n0 + wn * 32 + ni * 8 + t4 * 2;
                float v0 = acc[mi][ni][hf * 2], v1 = acc[mi][ni][hf * 2 + 1];
                *(__half2*)&C[(long)r * HDIM + cc] =
                    __floats2half2_rn(v0 * sigf(v0), v1 * sigf(v1));
            }
        }
        return;
    }

    // W-next split-K partials
    const int u = x - 256;
    const bool isW2 = (u >= 128);
    const int v = u & 127;
    const int z = v >> 3;
    const int tile = v & 7;
    const int bz = z >> 2, sp = z & 3;
    int m0, n0, lda, ldb, ldc;
    const __half *A, *B; float* C;
    if (!isW2) {
        m0 = (tile >> 1) * 128; n0 = (tile & 1) * 128;
        A = gZ1h + bz * S_LH + (long)(LSEQ - WBAND) * HDIM; lda = HDIM;
        B = qkvh + bz * S_L3D + (long)(LSEQ - WBAND) * L3D + DDIM; ldb = L3D;
        C = Wsp1 + (long)z * S_HD; ldc = DDIM;
    } else {
        m0 = (tile >> 2) * 128; n0 = (tile & 3) * 128;
        A = gZ2h + bz * S_LD + (long)(LSEQ - WBAND) * DDIM; lda = DDIM;
        B = X2h + bz * S_LH + (long)(LSEQ - WBAND) * HDIM; ldb = HDIM;
        C = Wsp2 + (long)z * S_DH; ldc = HDIM;
    }
    const float* wsc = wfac + (long)bz * LSEQ + (LSEQ - WBAND);
    const int k0 = sp * 32;
    st_km_scaled(dynsm, A, lda, m0, k0, wsc, tid);
    ld_kn(sb + 10240, B, ldb, n0, k0, tid);
    cp_commit(); cp_wait0();
    __syncthreads();
    compute_tile<1, 0>(sb, sb + 10240, acc, lane, wm, wn);
#pragma unroll
    for (int mi = 0; mi < 4; mi++)
#pragma unroll
    for (int hf = 0; hf < 2; hf++) {
        const int r = m0 + wm * 64 + mi * 16 + g + hf * 8;
#pragma unroll
        for (int ni = 0; ni < 4; ni++) {
            const int cc = n0 + wn * 32 + ni * 8 + t4 * 2;
            *(float2*)&C[(long)r * ldc + cc] =
                make_float2(acc[mi][ni][hf * 2], acc[mi][ni][hf * 2 + 1]);
        }
    }
}

// ---------------- S2-gen ----------------
__global__ void __launch_bounds__(256, 2) s2_k(
    const __half* __restrict__ X2nh, const __half* __restrict__ X2h,
    __half* __restrict__ Sh, const float* __restrict__ lrv,
    const double* __restrict__ LcD)
{
    const int t = blockIdx.x;
    const int bz = t / 31, tt = t - bz * 31;
    const int mm = (tt < 16) ? tt : tt - 15;
    const int nn = (tt < 16) ? tt : tt - 16;
    const int m0 = mm * 128, n0 = nn * 128;

    extern __shared__ __align__(16) char dynsm[];
    const uint32_t sb = smem_u32(dynsm);
    __shared__ float sFr[128], sFc[128];
    const int tid = threadIdx.x, w = tid >> 5, lane = tid & 31;
    const int wm = w >> 2, wn = w & 3;
    float acc[4][4][4] = {};

    gemm_loop<1>(sb, X2nh + bz * S_LH, HDIM, m0, X2h + bz * S_LH, HDIM, n0,
                 0, HDIM, acc, tid, lane, wm, wn);
    s_epilogue(acc, Sh + (long)bz * S_LL, m0, n0,
               lrv + (long)bz * LSEQ, LcD + (long)bz * LSEQ, sFr, sFc, tid, lane, wm, wn);
}

// ---------------- attn2 (-> output, first) + W-reduce (filler) merged ----------------
__global__ void __launch_bounds__(256, 2) attnred_k(
    const __half* __restrict__ X2nh, const __half* __restrict__ W2h,
    const __half* __restrict__ Sh, const __half* __restrict__ gZ2h,
    float* __restrict__ Z2o, const float* __restrict__ cexp,
    const float* __restrict__ Wsp1, const float* __restrict__ W1,
    const float* __restrict__ Wsp2, const float* __restrict__ W2,
    const float* __restrict__ clast,
    float* __restrict__ W1o, float* __restrict__ W2o)
{
    const int x = blockIdx.x;
    const int tid = threadIdx.x;

    if (x >= 128) {
        const int u = x - 128;
        const int sel = u >> 9, rem = u & 511;
        const int b = rem >> 7, blk = rem & 127;
        const float *P = sel ? Wsp2 : Wsp1, *W = sel ? W2 : W1;
        float* out = sel ? W2o : W1o;
        const long MN = S_HD;
        const int idx = blk * 256 + tid;
        const float4* Pb = (const float4*)(P + (long)b * NSPLIT * MN);
        float4 s = make_float4(0.f, 0.f, 0.f, 0.f);
#pragma unroll
        for (int sp = 0; sp < NSPLIT; sp++) {
            float4 v = Pb[(long)sp * (MN >> 2) + idx];
            s.x += v.x; s.y += v.y; s.z += v.z; s.w += v.w;
        }
        const float c = clast[b];
        float4 wv = ((const float4*)(W + (long)b * MN))[idx];
        ((float4*)(out + (long)b * MN))[idx] =
            make_float4(c * wv.x - s.x, c * wv.y - s.y, c * wv.z - s.z, c * wv.w - s.w);
        return;
    }

    const int bz = x >> 5, rem = x & 31;
    const int m0 = (rem >> 1) * 128, n0 = (rem & 1) * 128;
    extern __shared__ __align__(16) char dynsm[];
    const uint32_t sb = smem_u32(dynsm);
    const int w = tid >> 5, lane = tid & 31;
    const int wm = w >> 2, wn = w & 3, g = lane >> 2, t4 = lane & 3;
    float acc[4][4][4] = {};
    const float* ce = cexp + (long)bz * LSEQ;

    if (ce[m0] >= 1e-30f) {
        gemm_loop<1>(sb, X2nh + bz * S_LH, HDIM, m0, W2h + bz * S_DH, HDIM, n0,
                     0, HDIM, acc, tid, lane, wm, wn);
#pragma unroll
        for (int mi = 0; mi < 4; mi++)
#pragma unroll
        for (int hf = 0; hf < 2; hf++) {
            const float s = ce[m0 + wm * 64 + mi * 16 + g + hf * 8];
#pragma unroll
            for (int ni = 0; ni < 4; ni++) {
                acc[mi][ni][hf * 2 + 0] *= s;
                acc[mi][ni][hf * 2 + 1] *= s;
            }
        }
        cp_wait0(); __syncthreads();
    }
    const int kbeg = (m0 >= 128) ? m0 - BANDBACK : 0;
    gemm_loop<0>(sb, Sh + (long)bz * S_LL, LSEQ, m0, gZ2h + bz * S_LD, DDIM, n0,
                 kbeg, m0 + 128, acc, tid, lane, wm, wn);
    float* C = Z2o + bz * S_LD;
#pragma unroll
    for (int mi = 0; mi < 4; mi++)
#pragma unroll
    for (int hf = 0; hf < 2; hf++) {
        const int r = m0 + wm * 64 + mi * 16 + g + hf * 8;
#pragma unroll
        for (int ni = 0; ni < 4; ni++) {
            const int cc = n0 + wn * 32 + ni * 8 + t4 * 2;
            *(float2*)&C[(long)r * DDIM + cc] =
                make_float2(acc[mi][ni][hf * 2], acc[mi][ni][hf * 2 + 1]);
        }
    }
}

// ---------------- merged prep (+ folded-M gemm + b1add) ----------------
#define CN1 ((long)BATCH*LSEQ*DDIM)
#define CN2 (CN1 + (long)BATCH*HDIM*DDIM)
#define CN3 (CN2 + (long)BATCH*DDIM*HDIM)
#define PB_CONV ((int)(CN3 / 1024))
#define PB_ROW  (PB_CONV + 1024)
#define PB_T1   (PB_ROW + 192)
#define PB_T2   (PB_T1 + 512)
#define PB_BIAS (PB_T2 + 1)
#define PB_MG   (PB_BIAS + 128)     // M-gemm: 4b x 8h-tiles x 4d-tiles
#define PB_B1   (PB_MG + 256)       // b1add: 2048 warp-dots / 8
#define PB_ALL  PB_B1
__global__ void prep_k(const float* __restrict__ x,  __half* __restrict__ xh,
                       const float* __restrict__ W1, __half* __restrict__ W1h,
                       const float* __restrict__ W2, __half* __restrict__ W2h,
                       const float* __restrict__ wlr, const float* __restrict__ wwd,
                       const float* __restrict__ blr, const float* __restrict__ bwd,
                       float* __restrict__ lrraw, float* __restrict__ wdraw,
                       const float* __restrict__ Wq, const float* __restrict__ Wk,
                       const float* __restrict__ Wv, __half* __restrict__ WqkvT,
                       __half* __restrict__ W2Th, __half* __restrict__ Mh,
                       const float* __restrict__ bq, const float* __restrict__ bk,
                       const float* __restrict__ bv, float* __restrict__ bqkv,
                       float* __restrict__ b1add)
{
    const int bx = blockIdx.x, tid = threadIdx.x;
    __shared__ float tb[32][33];
    __shared__ float W1s[64][17], Wks[64][17];

    if (bx < PB_CONV) {
        const long e = (long)(bx * 256 + tid) * 4;
        const float* src; __half* dst; long off;
        if (e < CN1)      { src = x;  dst = xh;  off = e; }
        else if (e < CN2) { src = W1; dst = W1h; off = e - CN1; }
        else              { src = W2; dst = W2h; off = e - CN2; }
        float4 v = *(const float4*)(src + off);
        *(__half2*)(dst + off)     = __floats2half2_rn(v.x, v.y);
        *(__half2*)(dst + off + 2) = __floats2half2_rn(v.z, v.w);
        return;
    }
    if (bx < PB_ROW) {
        const int row = (bx - PB_CONV) * 8 + (tid >> 5);
        const int lane = tid & 31;
        const float* xr = x + (long)row * DDIM;
        float s1 = 0.f, s2 = 0.f;
#pragma unroll
        for (int i = lane; i < DDIM; i += 32) {
            float xv = xr[i];
            s1 += xv * wlr[i];
            s2 += xv * wwd[i];
        }
#pragma unroll
        for (int o = 16; o; o >>= 1) {
            s1 += __shfl_xor_sync(0xffffffffu, s1, o);
            s2 += __shfl_xor_sync(0xffffffffu, s2, o);
        }
        if (!lane) { lrraw[row] = s1 + blr[0]; wdraw[row] = s2 + bwd[0]; }
        return;
    }
    const int tx = tid & 31, ty = tid >> 5;
    if (bx < PB_T1) {
        const int u = bx - PB_ROW;
        const int z = u >> 6, b = u & 63;
        const int c0 = (b & 7) * 32, r0 = (b >> 3) * 32;
        const float* in = (z == 0) ? Wq : (z == 1) ? Wk : Wv;
        __half* out = WqkvT + (long)z * DDIM * DDIM;
#pragma unroll
        for (int k = 0; k < 4; k++)
            tb[ty + k * 8][tx] = in[(long)(r0 + ty + k * 8) * DDIM + c0 + tx];
        __syncthreads();
#pragma unroll
        for (int k = 0; k < 4; k++)
            out[(long)(c0 + ty + k * 8) * DDIM + r0 + tx] = __float2half_rn(tb[tx][ty + k * 8]);
        return;
    }
    if (bx < PB_T2) {
        const int u = bx - PB_T1;
        const int b = u >> 7, v = u & 127;
        const int c0 = (v & 15) * 32, r0 = (v >> 4) * 32;
        const float* in = W2 + (long)b * S_DH;
        __half* out = W2Th + (long)b * S_HD;
#pragma unroll
        for (int k = 0; k < 4; k++)
            tb[ty + k * 8][tx] = in[(long)(r0 + ty + k * 8) * HDIM + c0 + tx];
        __syncthreads();
#pragma unroll
        for (int k = 0; k < 4; k++)
            out[(long)(c0 + ty + k * 8) * DDIM + r0 + tx] = __float2half_rn(tb[tx][ty + k * 8]);
        return;
    }
    if (bx < PB_BIAS) {
        for (int j = tid; j < 768; j += 256)
            bqkv[j] = (j < 256) ? bq[j] : (j < 512) ? bk[j - 256] : bv[j - 512];
        return;
    }
    if (bx < PB_MG) {
        // M-gemm (fp32 SIMT): Mh[b][h][d] = sum_e W1[b,h,e] * Wk[d,e]
        const int u = bx - PB_BIAS;
        const int b = u >> 5, rem = u & 31;
        const int h0 = (rem >> 2) * 64, d0 = (rem & 3) * 64;
        const float* W1b = W1 + (long)b * S_HD;
        float acc[4][4] = {};
        const int txx = tid & 15, tyy = tid >> 4;   // 16x16 threads, 4x4 microtile
        for (int e0 = 0; e0 < 256; e0 += 16) {
#pragma unroll
            for (int i = 0; i < 4; i++) {
                int idx = i * 256 + tid, row = idx >> 4, col = idx & 15;
                W1s[row][col] = W1b[(long)(h0 + row) * 256 + e0 + col];
                Wks[row][col] = Wk[(long)(d0 + row) * 256 + e0 + col];
            }
            __syncthreads();
#pragma unroll
            for (int e = 0; e < 16; e++) {
                float av[4], bv4[4];
#pragma unroll
                for (int i = 0; i < 4; i++) { av[i] = W1s[tyy * 4 + i][e]; bv4[i] = Wks[txx * 4 + i][e]; }
#pragma unroll
                for (int i = 0; i < 4; i++)
#pragma unroll
                    for (int j = 0; j < 4; j++) acc[i][j] += av[i] * bv4[j];
            }
            __syncthreads();
        }
        __half* Mb = Mh + (long)b * S_HD;
#pragma unroll
        for (int i = 0; i < 4; i++)
#pragma unroll
        for (int j = 0; j < 4; j++)
            Mb[(long)(h0 + tyy * 4 + i) * 256 + d0 + txx * 4 + j] = __float2half_rn(acc[i][j]);
        return;
    }
    // b1add: warp-per-output, b1add[b][h] = sum_e bk[e]*W1[b,h,e]
    {
        const int u = bx - PB_MG;
        const int idx = u * 8 + (tid >> 5);
        const int lane = tid & 31;
        const int b = idx >> 9, h = idx & 511;
        const float* W1r = W1 + (long)b * S_HD + (long)h * 256;
        float s = 0.f;
#pragma unroll
        for (int e = lane; e < 256; e += 32) s += bk[e] * W1r[e];
#pragma unroll
        for (int o = 16; o; o >>= 1) s += __shfl_xor_sync(0xffffffffu, s, o);
        if (!lane) b1add[(long)b * HDIM + h] = s;
    }
}

// ---------------- launch ----------------
extern "C" void kernel_launch(void* const* d_in, const int* in_sizes, int n_in,
                              void* d_out, int out_size)
{
    const float* x   = (const float*)d_in[0];
    const float* W1  = (const float*)d_in[1];
    const float* W2  = (const float*)d_in[2];
    const float* Wq  = (const float*)d_in[3];
    const float* bq  = (const float*)d_in[4];
    const float* Wk  = (const float*)d_in[5];
    const float* bk  = (const float*)d_in[6];
    const float* Wv  = (const float*)d_in[7];
    const float* bv  = (const float*)d_in[8];
    const float* wlr = (const float*)d_in[9];
    const float* blr = (const float*)d_in[10];
    const float* wwd = (const float*)d_in[11];
    const float* bwd = (const float*)d_in[12];
    const float* lbl = (const float*)d_in[13];
    const float* lbw = (const float*)d_in[14];

    float* Z2o = (float*)d_out;
    float* W1o = Z2o + (long)BATCH * LSEQ * DDIM;
    float* W2o = W1o + (long)BATCH * HDIM * DDIM;

    __half *xh, *WqkvT, *Mh, *W1h, *W2h, *W2Th, *qkvh, *Z1h, *X2h, *gZ2h, *gZ1h, *X2nh, *Sh;
    float *bqkv, *b1add, *qkvf, *Wsp1, *Wsp2;
    float *lrv, *cexp, *wfac, *clast, *lrraw, *wdraw;
    double* LcD;
    cudaGetSymbolAddress((void**)&xh,    g_xh);
    cudaGetSymbolAddress((void**)&WqkvT, g_WqkvT);
    cudaGetSymbolAddress((void**)&Mh,    g_Mh);
    cudaGetSymbolAddress((void**)&bqkv,  g_bqkv);
    cudaGetSymbolAddress((void**)&b1add, g_b1add);
    cudaGetSymbolAddress((void**)&W1h,   g_W1h);
    cudaGetSymbolAddress((void**)&W2h,   g_W2h);
    cudaGetSymbolAddress((void**)&W2Th,  g_W2Th);
    cudaGetSymbolAddress((void**)&qkvf,  g_qkvf);
    cudaGetSymbolAddress((void**)&qkvh,  g_qkvh);
    cudaGetSymbolAddress((void**)&Z1h,   g_Z1h);
    cudaGetSymbolAddress((void**)&X2h,   g_X2h);
    cudaGetSymbolAddress((void**)&gZ2h,  g_gZ2h);
    cudaGetSymbolAddress((void**)&gZ1h,  g_gZ1h);
    cudaGetSymbolAddress((void**)&X2nh,  g_X2nh);
    cudaGetSymbolAddress((void**)&Sh,    g_Sh);
    cudaGetSymbolAddress((void**)&Wsp1,  g_Wsp1);
    cudaGetSymbolAddress((void**)&Wsp2,  g_Wsp2);
    cudaGetSymbolAddress((void**)&lrv,   g_lr);
    cudaGetSymbolAddress((void**)&LcD,   g_LcD);
    cudaGetSymbolAddress((void**)&cexp,  g_cexp);
    cudaGetSymbolAddress((void**)&wfac,  g_wfac);
    cudaGetSymbolAddress((void**)&clast, g_clast);
    cudaGetSymbolAddress((void**)&lrraw, g_lrraw);
    cudaGetSymbolAddress((void**)&wdraw, g_wdraw);

    cudaFuncSetAttribute(qkvext_k,  cudaFuncAttributeMaxDynamicSharedMemorySize, SMEM_DYN);
    cudaFuncSetAttribute(gz1_k,     cudaFuncAttributeMaxDynamicSharedMemorySize, SMEM_DYN);
    cudaFuncSetAttribute(gzs1_k,    cudaFuncAttributeMaxDynamicSharedMemorySize, SMEM_DYN);
    cudaFuncSetAttribute(attn1wp_k, cudaFuncAttributeMaxDynamicSharedMemorySize, SMEM_DYN);
    cudaFuncSetAttribute(s2_k,      cudaFuncAttributeMaxDynamicSharedMemorySize, SMEM_DYN);
    cudaFuncSetAttribute(attnred_k, cudaFuncAttributeMaxDynamicSharedMemorySize, SMEM_DYN);

    dim3 blk(256);

    // 1: prep (converts + rowstats + transposes + bias + M-gemm + b1add)
    prep_k<<<PB_ALL, 256>>>(x, xh, W1, W1h, W2, W2h, wlr, wwd, blr, bwd, lrraw, wdraw,
                            Wq, Wk, Wv, WqkvT, W2Th, Mh, bq, bk, bv, bqkv, b1add);

    // 2: extended QKV (Q,K,V,Z1,X2) + scan
    qkvext_k<<<dim3(11, 16, BATCH), blk, SMEM_DYN>>>(
        xh, WqkvT, Mh, qkvf, qkvh, Z1h, X2h, bqkv, b1add,
        lrraw, wdraw, lbl, lbw, lrv, LcD, cexp, wfac, clast);

    // 3: gZ2 + S1-gen (merged)
    gzs1_k<<<dim3(63, 1, BATCH), blk, SMEM_DYN>>>(
        X2h, W2h, qkvf, gZ2h, qkvh, Sh, lrv, LcD);

    // 4: gZ1 = silu'(Z1) * (gZ2 @ W2)
    gz1_k<<<dim3(4, 16, BATCH), blk, SMEM_DYN>>>(
        gZ2h, S_LD, DDIM,  W2Th, S_HD, DDIM,  gZ1h, S_LH, HDIM,  DDIM,
        Z1h, S_LH, HDIM);

    // 5: attn1 (fused, band 96) + W-next partials
    attn1wp_k<<<dim3(512, 1, 1), blk, SMEM_DYN>>>(
        qkvh, W1h, Sh, gZ1h, X2nh, cexp, gZ2h, X2h, Wsp1, Wsp2, wfac);

    // 6: S2-gen
    s2_k<<<dim3(124, 1, 1), blk, SMEM_DYN>>>(X2nh, X2h, Sh, lrv, LcD);

    // 7: attn2 (band 96) -> output + W-reduce filler
    attnred_k<<<dim3(128 + 1024, 1, 1), blk, SMEM_DYN>>>(
        X2nh, W2h, Sh, gZ2h, Z2o, cexp, Wsp1, W1, Wsp2, W2, clast, W1o, W2o);
}

// round 15
// speedup vs baseline: 1.2861x; 1.2861x over previous
#include <cuda_runtime.h>
#include <cuda_fp16.h>
#include <cstdint>

#define BATCH 4
#define LSEQ  2048
#define DDIM  256
#define HDIM  512
#define WBAND 128
#define NSPLIT 4
#define L3D   (3*DDIM)
#define BANDBACK 96   // attn band: k in [m0-BANDBACK, m0+128)

#define S_LD  ((long)LSEQ*DDIM)
#define S_LH  ((long)LSEQ*HDIM)
#define S_LL  ((long)LSEQ*LSEQ)
#define S_HD  ((long)HDIM*DDIM)
#define S_DH  ((long)DDIM*HDIM)
#define S_L3D ((long)LSEQ*L3D)

// ---------------- scratch ----------------
__device__ __half g_xh   [BATCH*LSEQ*DDIM];
__device__ __half g_WqkvT[3*DDIM*DDIM];
__device__ float  g_bqkv [3*DDIM];
__device__ __half g_W1h  [BATCH*HDIM*DDIM];
__device__ __half g_W2h  [BATCH*DDIM*HDIM];
__device__ __half g_W2Th [BATCH*HDIM*DDIM];
__device__ float  g_qkvf [BATCH*LSEQ*L3D];
__device__ __half g_qkvh [BATCH*LSEQ*L3D];
__device__ __half g_Z1h  [BATCH*LSEQ*HDIM];
__device__ __half g_X2h  [BATCH*LSEQ*HDIM];
__device__ __half g_gZ2h [BATCH*LSEQ*DDIM];
__device__ __half g_gZ1h [BATCH*LSEQ*HDIM];
__device__ __half g_X2nh [BATCH*LSEQ*HDIM];
__device__ __half g_Sh   [(size_t)BATCH*LSEQ*LSEQ];
__device__ float  g_Wsp1 [BATCH*NSPLIT*HDIM*DDIM];
__device__ float  g_Wsp2 [BATCH*NSPLIT*DDIM*HDIM];
__device__ float  g_lr   [BATCH*LSEQ];
__device__ double g_LcD  [BATCH*LSEQ];
__device__ float  g_cexp [BATCH*LSEQ];
__device__ float  g_wfac [BATCH*LSEQ];
__device__ float  g_clast[BATCH];
__device__ float  g_lrraw[BATCH*LSEQ];
__device__ float  g_wdraw[BATCH*LSEQ];

// ---------------- helpers ----------------
__device__ __forceinline__ uint32_t smem_u32(const void* p) {
    return (uint32_t)__cvta_generic_to_shared(p);
}
__device__ __forceinline__ float sigf(float x) {
    return __fdividef(1.0f, 1.0f + __expf(-x));
}
__device__ __forceinline__ void cpasync16(uint32_t dst, const void* src) {
    asm volatile("cp.async.cg.shared.global [%0], [%1], 16;\n" :: "r"(dst), "l"(src));
}
__device__ __forceinline__ void cp_commit() { asm volatile("cp.async.commit_group;\n" ::: "memory"); }
__device__ __forceinline__ void cp_wait1()  { asm volatile("cp.async.wait_group 1;\n" ::: "memory"); }
__device__ __forceinline__ void cp_wait0()  { asm volatile("cp.async.wait_group 0;\n" ::: "memory"); }
__device__ __forceinline__ void ldsm4(uint32_t& r0, uint32_t& r1, uint32_t& r2, uint32_t& r3, uint32_t a) {
    asm volatile("ldmatrix.sync.aligned.m8n8.x4.shared.b16 {%0,%1,%2,%3}, [%4];\n"
                 : "=r"(r0), "=r"(r1), "=r"(r2), "=r"(r3) : "r"(a));
}
__device__ __forceinline__ void ldsm4t(uint32_t& r0, uint32_t& r1, uint32_t& r2, uint32_t& r3, uint32_t a) {
    asm volatile("ldmatrix.sync.aligned.m8n8.x4.trans.shared.b16 {%0,%1,%2,%3}, [%4];\n"
                 : "=r"(r0), "=r"(r1), "=r"(r2), "=r"(r3) : "r"(a));
}
__device__ __forceinline__ void mma16816(float* d, const uint32_t* a, uint32_t b0, uint32_t b1) {
    asm volatile("mma.sync.aligned.m16n8k16.row.col.f32.f16.f16.f32 "
                 "{%0,%1,%2,%3}, {%4,%5,%6,%7}, {%8,%9}, {%0,%1,%2,%3};\n"
                 : "+f"(d[0]), "+f"(d[1]), "+f"(d[2]), "+f"(d[3])
                 : "r"(a[0]), "r"(a[1]), "r"(a[2]), "r"(a[3]), "r"(b0), "r"(b1));
}

#define SLOT     20480
#define SMEM_DYN (3 * SLOT)

// stage loaders
__device__ __forceinline__ void ld_mk(uint32_t dst, const __half* src, int ld, int r0, int k0, int tid) {
#pragma unroll
    for (int i = 0; i < 2; i++) {
        int c = i * 256 + tid, row = c >> 2, ch = c & 3;
        cpasync16(dst + row * 80 + ch * 16, src + (long)(r0 + row) * ld + k0 + ch * 8);
    }
}
__device__ __forceinline__ void ld_kn(uint32_t dst, const __half* src, int ld, int n0, int k0, int tid) {
#pragma unroll
    for (int i = 0; i < 2; i++) {
        int c = i * 256 + tid, k = c >> 4, ch = c & 15;
        cpasync16(dst + k * 272 + ch * 16, src + (long)(k0 + k) * ld + n0 + ch * 8);
    }
}
__device__ __forceinline__ void st_km_scaled(char* slotp, const __half* A, int lda, int m0, int k0,
                                             const float* wsc, int tid) {
    __half* smA = (__half*)slotp;
#pragma unroll
    for (int i = 0; i < 16; i++) {
        int e = i * 256 + tid, k = e >> 7, m = e & 127;
        smA[k * 136 + m] = __float2half_rn(__half2float(A[(long)(k0 + k) * lda + m0 + m]) * wsc[k0 + k]);
    }
}

// ---------------- fragment loaders ----------------
template<int TB>
__device__ __forceinline__ void ldB_frag(uint32_t bb, int ks, uint32_t (&Bp)[4][2], int lane, int wn) {
#pragma unroll
    for (int nj = 0; nj < 2; nj++) {
        uint32_t r0, r1, r2, r3;
        if (TB == 1) {
            uint32_t addr = bb + (uint32_t)((wn * 32 + nj * 16 + (lane & 15)) * 80
                                            + (ks * 16 + (lane >> 4) * 8) * 2);
            ldsm4(r0, r1, r2, r3, addr);
            Bp[nj*2][0] = r0; Bp[nj*2][1] = r2; Bp[nj*2+1][0] = r1; Bp[nj*2+1][1] = r3;
        } else {
            uint32_t addr = bb + (uint32_t)((ks * 16 + (lane & 15)) * 272
                                            + (wn * 32 + nj * 16 + (lane >> 4) * 8) * 2);
            ldsm4t(r0, r1, r2, r3, addr);
            Bp[nj*2][0] = r0; Bp[nj*2][1] = r1; Bp[nj*2+1][0] = r2; Bp[nj*2+1][1] = r3;
        }
    }
}
template<int TA>
__device__ __forceinline__ void ldA_frag(uint32_t ab, int ks, int mi, uint32_t (&Af)[4], int lane, int wm) {
    if (TA == 0) {
        uint32_t addr = ab + (uint32_t)((wm * 64 + mi * 16 + (lane & 15)) * 80
                                        + (ks * 16 + (lane >> 4) * 8) * 2);
        ldsm4(Af[0], Af[1], Af[2], Af[3], addr);
    } else {
        uint32_t addr = ab + (uint32_t)((ks * 16 + (lane & 7) + ((lane >> 4) << 3)) * 272
                                        + (wm * 64 + mi * 16 + ((lane >> 3) & 1) * 8) * 2);
        ldsm4t(Af[0], Af[1], Af[2], Af[3], addr);
    }
}

template<int TA, int TB>
__device__ __forceinline__ void compute_tile(uint32_t ab, uint32_t bb,
                                             float (&acc)[4][4][4], int lane, int wm, int wn)
{
    uint32_t Bp[2][4][2];
    uint32_t Af[2][4];
    ldB_frag<TB>(bb, 0, Bp[0], lane, wn);
    ldA_frag<TA>(ab, 0, 0, Af[0], lane, wm);
    ldB_frag<TB>(bb, 1, Bp[1], lane, wn);
#pragma unroll
    for (int ks = 0; ks < 2; ks++) {
#pragma unroll
        for (int mi = 0; mi < 4; mi++) {
            if (mi < 3)       ldA_frag<TA>(ab, ks, mi + 1, Af[(mi + 1) & 1], lane, wm);
            else if (ks == 0) ldA_frag<TA>(ab, 1, 0,      Af[0],            lane, wm);
#pragma unroll
            for (int ni = 0; ni < 4; ni++)
                mma16816(acc[mi][ni], Af[mi & 1], Bp[ks][ni][0], Bp[ks][ni][1]);
        }
    }
}

// full mainloop
template<int TB>
__device__ __forceinline__ void gemm_loop(uint32_t sb,
                                          const __half* A, int lda, int m0,
                                          const __half* B, int ldb, int n0,
                                          int kbeg, int kend, float (&acc)[4][4][4],
                                          int tid, int lane, int wm, int wn)
{
    const int nkt = (kend - kbeg) >> 5;
    ld_mk(sb, A, lda, m0, kbeg, tid);
    if (TB == 1) ld_mk(sb + 10240, B, ldb, n0, kbeg, tid);
    else         ld_kn(sb + 10240, B, ldb, n0, kbeg, tid);
    cp_commit();
    if (nkt > 1) {
        ld_mk(sb + SLOT, A, lda, m0, kbeg + 32, tid);
        if (TB == 1) ld_mk(sb + SLOT + 10240, B, ldb, n0, kbeg + 32, tid);
        else         ld_kn(sb + SLOT + 10240, B, ldb, n0, kbeg + 32, tid);
    }
    cp_commit();
    for (int kt = 0; kt < nkt; kt++) {
        cp_wait1(); __syncthreads();
        if (kt + 2 < nkt) {
            int sl = (kt + 2) % 3;
            int k0 = kbeg + (kt + 2) * 32;
            ld_mk(sb + sl * SLOT, A, lda, m0, k0, tid);
            if (TB == 1) ld_mk(sb + sl * SLOT + 10240, B, ldb, n0, k0, tid);
            else         ld_kn(sb + sl * SLOT + 10240, B, ldb, n0, k0, tid);
        }
        cp_commit();
        uint32_t ab = sb + (uint32_t)(kt % 3) * SLOT;
        compute_tile<0, TB>(ab, ab + 10240, acc, lane, wm, wn);
    }
}

// negated masked-decay S epilogue
__device__ __forceinline__ void s_epilogue(float (&acc)[4][4][4], __half* ShB,
                                           int m0, int n0,
                                           const float* lrv, const double* LcD,
                                           float* sFr, float* sFc,
                                           int tid, int lane, int wm, int wn)
{
    const int g = lane >> 2, t4 = lane & 3;
    if (tid < 128) sFr[tid] = __expf((float)(LcD[m0 + tid] - LcD[m0]));
    else { int i = tid - 128; sFc[i] = __expf((float)(LcD[m0] - LcD[n0 + i])) * lrv[n0 + i]; }
    __syncthreads();
#pragma unroll
    for (int mi = 0; mi < 4; mi++)
#pragma unroll
    for (int hf = 0; hf < 2; hf++) {
        const int r = m0 + wm * 64 + mi * 16 + g + hf * 8;
        const float f1 = sFr[r - m0];
#pragma unroll
        for (int ni = 0; ni < 4; ni++) {
            const int cc = n0 + wn * 32 + ni * 8 + t4 * 2;
            const int cl = wn * 32 + ni * 8 + t4 * 2;
            float v0 = acc[mi][ni][hf * 2], v1 = acc[mi][ni][hf * 2 + 1];
            float o0 = (cc     <= r) ? -(v0 * f1 * sFc[cl])     : 0.f;
            float o1 = (cc + 1 <= r) ? -(v1 * f1 * sFc[cl + 1]) : 0.f;
            *(__half2*)&ShB[(long)r * LSEQ + cc] = __floats2half2_rn(o0, o1);
        }
    }
}

// ---------------- QKV GEMM + scan merged ----------------
__global__ void __launch_bounds__(256, 2) qkvscan_k(
    const __half* __restrict__ xh, const __half* __restrict__ WqkvT,
    float* __restrict__ qkvf, __half* __restrict__ qkvh,
    const float* __restrict__ bqkv,
    const float* __restrict__ lrraw, const float* __restrict__ wdraw,
    const float* __restrict__ lbl, const float* __restrict__ lbw,
    float* __restrict__ lr, double* __restrict__ LcD,
    float* __restrict__ cexp, float* __restrict__ wfac,
    float* __restrict__ clast)
{
    const int tid = threadIdx.x;
    if (blockIdx.x == 6) {
        if (blockIdx.y != 0) return;
        const int b = blockIdx.z;
        __shared__ double ssum[256];
        __shared__ double sLast;
        const float ewd = expf(lbw[0]);
        const float elr = expf(lbl[0]);
        double loc[8];
        double tot = 0.0;
        const int base = b * LSEQ + tid * 8;
#pragma unroll
        for (int i = 0; i < 8; i++) {
            float sig = 1.f / (1.f + expf(-wdraw[base + i]));
            double lw = log(1.0 - (double)ewd * (double)sig);
            tot += lw;
            loc[i] = tot;
        }
        ssum[tid] = tot;
        __syncthreads();
        for (int off = 1; off < 256; off <<= 1) {
            double v = (tid >= off) ? ssum[tid - off] : 0.0;
            __syncthreads();
            ssum[tid] += v;
            __syncthreads();
        }
        double excl = (tid == 0) ? 0.0 : ssum[tid - 1];
        if (tid == 255) sLast = ssum[255];
        __syncthreads();
        double last = sLast;
#pragma unroll
        for (int i = 0; i < 8; i++) {
            double Lc = excl + loc[i];
            LcD[base + i] = Lc;
            cexp[base + i] = (float)exp(Lc);
            float l_r = elr / (1.f + expf(-lrraw[base + i]));
            lr[base + i] = l_r;
            wfac[base + i] = (float)((double)l_r * exp(last - Lc));
        }
        if (tid == 0) clast[b] = (float)exp(last);
        return;
    }

    const int bz = blockIdx.z;
    const int m0 = blockIdx.y * 128, n0 = blockIdx.x * 128;
    const __half* A = xh + bz * S_LD;
    float*  Cf = qkvf + bz * S_L3D;
    __half* Ch = qkvh + bz * S_L3D;

    extern __shared__ __align__(16) char dynsm[];
    const uint32_t sb = smem_u32(dynsm);
    const int w = tid >> 5, lane = tid & 31;
    const int wm = w >> 2, wn = w & 3, g = lane >> 2, t4 = lane & 3;

    float acc[4][4][4] = {};
    gemm_loop<1>(sb, A, DDIM, m0, WqkvT, DDIM, n0, 0, DDIM, acc, tid, lane, wm, wn);

#pragma unroll
    for (int mi = 0; mi < 4; mi++)
#pragma unroll
    for (int hf = 0; hf < 2; hf++) {
        const int r = m0 + wm * 64 + mi * 16 + g + hf * 8;
#pragma unroll
        for (int ni = 0; ni < 4; ni++) {
            const int cc = n0 + wn * 32 + ni * 8 + t4 * 2;
            float v0 = acc[mi][ni][hf * 2 + 0], v1 = acc[mi][ni][hf * 2 + 1];
            float o0 = v0 + bqkv[cc], o1 = v1 + bqkv[cc + 1];
            if (cc < 512)
                *(__half2*)&Ch[(long)r * L3D + cc] = __floats2half2_rn(o0, o1);
            else
                *(float2*)&Cf[(long)r * L3D + cc] = make_float2(o0, o1);
        }
    }
}

// ---------------- generic GEMM kernels ----------------
#define EPI_SILU2 3
#define EPI_G1    4

template<int EPI>
__global__ void __launch_bounds__(256, 2) hgemm_k(
    const __half* __restrict__ A, long sA, int lda,
    const __half* __restrict__ B, long sB, int ldb,
    __half* __restrict__ C, long sC, int ldc, int K,
    const __half* __restrict__ aux, long sAux, int ldaux,
    __half* __restrict__ out2, long sOut2)
{
    const int bz = blockIdx.z;
    const int m0 = blockIdx.y * 128, n0 = blockIdx.x * 128;
    A += bz * sA; B += bz * sB;
    C += bz * sC;
    if (aux)  aux  += bz * sAux;
    if (out2) out2 += bz * sOut2;

    extern __shared__ __align__(16) char dynsm[];
    const uint32_t sb = smem_u32(dynsm);
    const int tid = threadIdx.x, w = tid >> 5, lane = tid & 31;
    const int wm = w >> 2, wn = w & 3, g = lane >> 2, t4 = lane & 3;

    float acc[4][4][4] = {};
    gemm_loop<1>(sb, A, lda, m0, B, ldb, n0, 0, K, acc, tid, lane, wm, wn);

#pragma unroll
    for (int mi = 0; mi < 4; mi++)
#pragma unroll
    for (int hf = 0; hf < 2; hf++) {
        const int r = m0 + wm * 64 + mi * 16 + g + hf * 8;
#pragma unroll
        for (int ni = 0; ni < 4; ni++) {
            const int cc = n0 + wn * 32 + ni * 8 + t4 * 2;
            float v0 = acc[mi][ni][hf * 2 + 0], v1 = acc[mi][ni][hf * 2 + 1];
            if (EPI == EPI_SILU2) {
                *(__half2*)&C[(long)r * ldc + cc] = __floats2half2_rn(v0, v1);
                *(__half2*)&out2[(long)r * ldc + cc] =
                    __floats2half2_rn(v0 * sigf(v0), v1 * sigf(v1));
            } else { // EPI_G1: aux = Z1 (half)
                __half2 a2 = *(const __half2*)&aux[(long)r * ldaux + cc];
                float ax = __half2float(__low2half(a2));
                float ay = __half2float(__high2half(a2));
                float s0 = sigf(ax), s1 = sigf(ay);
                float i0 = ax * s0, i1 = ay * s1;
                *(__half2*)&C[(long)r * ldc + cc] = __floats2half2_rn(
                    (i0 + s0 * (1.f - i0)) * v0, (i1 + s1 * (1.f - i1)) * v1);
            }
        }
    }
}

// ---------------- gZ2 (32 tiles) + S1-gen (31 tiles) merged per batch ----------------
__global__ void __launch_bounds__(256, 2) gzs1_k(
    const __half* __restrict__ X2h, const __half* __restrict__ W2h,
    const float* __restrict__ qkvf, __half* __restrict__ gZ2h,
    const __half* __restrict__ qkvh, __half* __restrict__ Sh,
    const float* __restrict__ lrv, const double* __restrict__ LcD)
{
    const int bz = blockIdx.z;
    const int t = blockIdx.x;
    extern __shared__ __align__(16) char dynsm[];
    const uint32_t sb = smem_u32(dynsm);
    __shared__ float sFr[128], sFc[128];
    const int tid = threadIdx.x, w = tid >> 5, lane = tid & 31;
    const int wm = w >> 2, wn = w & 3, g = lane >> 2, t4 = lane & 3;
    float acc[4][4][4] = {};

    if (t < 32) {
        const int m0 = (t >> 1) * 128, n0 = (t & 1) * 128;
        gemm_loop<1>(sb, X2h + bz * S_LH, HDIM, m0, W2h + bz * S_DH, HDIM, n0,
                     0, HDIM, acc, tid, lane, wm, wn);
        const float* Vf = qkvf + bz * S_L3D + 2 * DDIM;
        __half* C = gZ2h + bz * S_LD;
#pragma unroll
        for (int mi = 0; mi < 4; mi++)
#pragma unroll
        for (int hf = 0; hf < 2; hf++) {
            const int r = m0 + wm * 64 + mi * 16 + g + hf * 8;
#pragma unroll
            for (int ni = 0; ni < 4; ni++) {
                const int cc = n0 + wn * 32 + ni * 8 + t4 * 2;
                float2 a = *(const float2*)&Vf[(long)r * L3D + cc];
                *(__half2*)&C[(long)r * DDIM + cc] = __floats2half2_rn(
                    acc[mi][ni][hf * 2] - a.x, acc[mi][ni][hf * 2 + 1] - a.y);
            }
        }
        return;
    }
    const int tt = t - 32;
    const int mm = (tt < 16) ? tt : tt - 15;
    const int nn = (tt < 16) ? tt : tt - 16;
    const int m0 = mm * 128, n0 = nn * 128;
    gemm_loop<1>(sb, qkvh + bz * S_L3D, L3D, m0, qkvh + bz * S_L3D + DDIM, L3D, n0,
                 0, DDIM, acc, tid, lane, wm, wn);
    s_epilogue(acc, Sh + bz * S_LL, m0, n0,
               lrv + (long)bz * LSEQ, LcD + (long)bz * LSEQ, sFr, sFc, tid, lane, wm, wn);
}

// ---------------- attn1 (fused cross+band) + W1/W2-next partials merged ----------------
__global__ void __launch_bounds__(256, 2) attn1wp_k(
    const __half* __restrict__ qkvh, const __half* __restrict__ W1h,
    const __half* __restrict__ Sh, const __half* __restrict__ gZ1h,
    __half* __restrict__ X2nh, const float* __restrict__ cexp,
    const __half* __restrict__ gZ2h, const __half* __restrict__ X2h,
    float* __restrict__ Wsp1, float* __restrict__ Wsp2,
    const float* __restrict__ wfac)
{
    extern __shared__ __align__(16) char dynsm[];
    const uint32_t sb = smem_u32(dynsm);
    const int tid = threadIdx.x, w = tid >> 5, lane = tid & 31;
    const int wm = w >> 2, wn = w & 3, g = lane >> 2, t4 = lane & 3;
    float acc[4][4][4] = {};
    const int x = blockIdx.x;

    if (x < 256) {
        const int bz = x >> 6, rem = x & 63;
        const int m0 = (rem >> 2) * 128, n0 = (rem & 3) * 128;
        const __half* Q = qkvh + bz * S_L3D;
        const float* ce = cexp + (long)bz * LSEQ;
        if (ce[m0] >= 1e-30f) {
            gemm_loop<1>(sb, Q, L3D, m0, W1h + bz * S_HD, DDIM, n0,
                         0, DDIM, acc, tid, lane, wm, wn);
#pragma unroll
            for (int mi = 0; mi < 4; mi++)
#pragma unroll
            for (int hf = 0; hf < 2; hf++) {
                const float s = ce[m0 + wm * 64 + mi * 16 + g + hf * 8];
#pragma unroll
                for (int ni = 0; ni < 4; ni++) {
                    acc[mi][ni][hf * 2 + 0] *= s;
                    acc[mi][ni][hf * 2 + 1] *= s;
                }
            }
            cp_wait0(); __syncthreads();
        }
        const int kbeg = (m0 >= 128) ? m0 - BANDBACK : 0;
        gemm_loop<0>(sb, Sh + bz * S_LL, LSEQ, m0, gZ1h + bz * S_LH, HDIM, n0,
                     kbeg, m0 + 128, acc, tid, lane, wm, wn);
        __half* C = X2nh + bz * S_LH;
#pragma unroll
        for (int mi = 0; mi < 4; mi++)
#pragma unroll
        for (int hf = 0; hf < 2; hf++) {
            const int r = m0 + wm * 64 + mi * 16 + g + hf * 8;
#pragma unroll
            for (int ni = 0; ni < 4; ni++) {
                const int cc = n0 + wn * 32 + ni * 8 + t4 * 2;
                float v0 = acc[mi][ni][hf * 2], v1 = acc[mi][ni][hf * 2 + 1];
                *(__half2*)&C[(long)r * HDIM + cc] =
                    __floats2half2_rn(v0 * sigf(v0), v1 * sigf(v1));
            }
        }
        return;
    }

    // W-next split-K partials (1 k-tile each, last WBAND=128 rows, NSPLIT=4)
    const int u = x - 256;
    const bool isW2 = (u >= 128);
    const int v = u & 127;
    const int z = v >> 3;
    const int tile = v & 7;
    const int bz = z >> 2, sp = z & 3;
    int m0, n0, lda, ldb, ldc;
    const __half *A, *B; float* C;
    if (!isW2) {
        m0 = (tile >> 1) * 128; n0 = (tile & 1) * 128;
        A = gZ1h + bz * S_LH + (long)(LSEQ - WBAND) * HDIM; lda = HDIM;
        B = qkvh + bz * S_L3D + (long)(LSEQ - WBAND) * L3D + DDIM; ldb = L3D;
        C = Wsp1 + (long)z * S_HD; ldc = DDIM;
    } else {
        m0 = (tile >> 2) * 128; n0 = (tile & 3) * 128;
        A = gZ2h + bz * S_LD + (long)(LSEQ - WBAND) * DDIM; lda = DDIM;
        B = X2h + bz * S_LH + (long)(LSEQ - WBAND) * HDIM; ldb = HDIM;
        C = Wsp2 + (long)z * S_DH; ldc = HDIM;
    }
    const float* wsc = wfac + (long)bz * LSEQ + (LSEQ - WBAND);
    const int k0 = sp * 32;
    st_km_scaled(dynsm, A, lda, m0, k0, wsc, tid);
    ld_kn(sb + 10240, B, ldb, n0, k0, tid);
    cp_commit(); cp_wait0();
    __syncthreads();
    compute_tile<1, 0>(sb, sb + 10240, acc, lane, wm, wn);
#pragma unroll
    for (int mi = 0; mi < 4; mi++)
#pragma unroll
    for (int hf = 0; hf < 2; hf++) {
        const int r = m0 + wm * 64 + mi * 16 + g + hf * 8;
#pragma unroll
        for (int ni = 0; ni < 4; ni++) {
            const int cc = n0 + wn * 32 + ni * 8 + t4 * 2;
            *(float2*)&C[(long)r * ldc + cc] =
                make_float2(acc[mi][ni][hf * 2], acc[mi][ni][hf * 2 + 1]);
        }
    }
}

// ---------------- S2-gen ----------------
__global__ void __launch_bounds__(256, 2) s2_k(
    const __half* __restrict__ X2nh, const __half* __restrict__ X2h,
    __half* __restrict__ Sh, const float* __restrict__ lrv,
    const double* __restrict__ LcD)
{
    const int t = blockIdx.x;
    const int bz = t / 31, tt = t - bz * 31;
    const int mm = (tt < 16) ? tt : tt - 15;
    const int nn = (tt < 16) ? tt : tt - 16;
    const int m0 = mm * 128, n0 = nn * 128;

    extern __shared__ __align__(16) char dynsm[];
    const uint32_t sb = smem_u32(dynsm);
    __shared__ float sFr[128], sFc[128];
    const int tid = threadIdx.x, w = tid >> 5, lane = tid & 31;
    const int wm = w >> 2, wn = w & 3;
    float acc[4][4][4] = {};

    gemm_loop<1>(sb, X2nh + bz * S_LH, HDIM, m0, X2h + bz * S_LH, HDIM, n0,
                 0, HDIM, acc, tid, lane, wm, wn);
    s_epilogue(acc, Sh + (long)bz * S_LL, m0, n0,
               lrv + (long)bz * LSEQ, LcD + (long)bz * LSEQ, sFr, sFc, tid, lane, wm, wn);
}

// ---------------- attn2 (-> output, first) + W-reduce (filler) merged ----------------
__global__ void __launch_bounds__(256, 2) attnred_k(
    const __half* __restrict__ X2nh, const __half* __restrict__ W2h,
    const __half* __restrict__ Sh, const __half* __restrict__ gZ2h,
    float* __restrict__ Z2o, const float* __restrict__ cexp,
    const float* __restrict__ Wsp1, const float* __restrict__ W1,
    const float* __restrict__ Wsp2, const float* __restrict__ W2,
    const float* __restrict__ clast,
    float* __restrict__ W1o, float* __restrict__ W2o)
{
    const int x = blockIdx.x;
    const int tid = threadIdx.x;

    if (x >= 128) {
        const int u = x - 128;
        const int sel = u >> 9, rem = u & 511;
        const int b = rem >> 7, blk = rem & 127;
        const float *P = sel ? Wsp2 : Wsp1, *W = sel ? W2 : W1;
        float* out = sel ? W2o : W1o;
        const long MN = S_HD;
        const int idx = blk * 256 + tid;
        const float4* Pb = (const float4*)(P + (long)b * NSPLIT * MN);
        float4 s = make_float4(0.f, 0.f, 0.f, 0.f);
#pragma unroll
        for (int sp = 0; sp < NSPLIT; sp++) {
            float4 v = Pb[(long)sp * (MN >> 2) + idx];
            s.x += v.x; s.y += v.y; s.z += v.z; s.w += v.w;
        }
        const float c = clast[b];
        float4 wv = ((const float4*)(W + (long)b * MN))[idx];
        ((float4*)(out + (long)b * MN))[idx] =
            make_float4(c * wv.x - s.x, c * wv.y - s.y, c * wv.z - s.z, c * wv.w - s.w);
        return;
    }

    const int bz = x >> 5, rem = x & 31;
    const int m0 = (rem >> 1) * 128, n0 = (rem & 1) * 128;
    extern __shared__ __align__(16) char dynsm[];
    const uint32_t sb = smem_u32(dynsm);
    const int w = tid >> 5, lane = tid & 31;
    const int wm = w >> 2, wn = w & 3, g = lane >> 2, t4 = lane & 3;
    float acc[4][4][4] = {};
    const float* ce = cexp + (long)bz * LSEQ;

    if (ce[m0] >= 1e-30f) {
        gemm_loop<1>(sb, X2nh + bz * S_LH, HDIM, m0, W2h + bz * S_DH, HDIM, n0,
                     0, HDIM, acc, tid, lane, wm, wn);
#pragma unroll
        for (int mi = 0; mi < 4; mi++)
#pragma unroll
        for (int hf = 0; hf < 2; hf++) {
            const float s = ce[m0 + wm * 64 + mi * 16 + g + hf * 8];
#pragma unroll
            for (int ni = 0; ni < 4; ni++) {
                acc[mi][ni][hf * 2 + 0] *= s;
                acc[mi][ni][hf * 2 + 1] *= s;
            }
        }
        cp_wait0(); __syncthreads();
    }
    const int kbeg = (m0 >= 128) ? m0 - BANDBACK : 0;
    gemm_loop<0>(sb, Sh + (long)bz * S_LL, LSEQ, m0, gZ2h + bz * S_LD, DDIM, n0,
                 kbeg, m0 + 128, acc, tid, lane, wm, wn);
    float* C = Z2o + bz * S_LD;
#pragma unroll
    for (int mi = 0; mi < 4; mi++)
#pragma unroll
    for (int hf = 0; hf < 2; hf++) {
        const int r = m0 + wm * 64 + mi * 16 + g + hf * 8;
#pragma unroll
        for (int ni = 0; ni < 4; ni++) {
            const int cc = n0 + wn * 32 + ni * 8 + t4 * 2;
            *(float2*)&C[(long)r * DDIM + cc] =
                make_float2(acc[mi][ni][hf * 2], acc[mi][ni][hf * 2 + 1]);
        }
    }
}

// ---------------- single merged prep ----------------
#define CN1 ((long)BATCH*LSEQ*DDIM)
#define CN2 (CN1 + (long)BATCH*HDIM*DDIM)
#define CN3 (CN2 + (long)BATCH*DDIM*HDIM)
#define PB_CONV ((int)(CN3 / 1024))
#define PB_ROW  (PB_CONV + 1024)
#define PB_T1   (PB_ROW + 192)
#define PB_T2   (PB_T1 + 512)
#define PB_ALL  (PB_T2 + 1)
__global__ void prep_k(const float* __restrict__ x,  __half* __restrict__ xh,
                       const float* __restrict__ W1, __half* __restrict__ W1h,
                       const float* __restrict__ W2, __half* __restrict__ W2h,
                       const float* __restrict__ wlr, const float* __restrict__ wwd,
                       const float* __restrict__ blr, const float* __restrict__ bwd,
                       float* __restrict__ lrraw, float* __restrict__ wdraw,
                       const float* __restrict__ Wq, const float* __restrict__ Wk,
                       const float* __restrict__ Wv, __half* __restrict__ WqkvT,
                       __half* __restrict__ W2Th,
                       const float* __restrict__ bq, const float* __restrict__ bk,
                       const float* __restrict__ bv, float* __restrict__ bqkv)
{
    const int bx = blockIdx.x, tid = threadIdx.x;
    if (bx < PB_CONV) {
        const long e = (long)(bx * 256 + tid) * 4;
        const float* src; __half* dst; long off;
        if (e < CN1)      { src = x;  dst = xh;  off = e; }
        else if (e < CN2) { src = W1; dst = W1h; off = e - CN1; }
        else              { src = W2; dst = W2h; off = e - CN2; }
        float4 v = *(const float4*)(src + off);
        *(__half2*)(dst + off)     = __floats2half2_rn(v.x, v.y);
        *(__half2*)(dst + off + 2) = __floats2half2_rn(v.z, v.w);
        return;
    }
    if (bx < PB_ROW) {
        const int row = (bx - PB_CONV) * 8 + (tid >> 5);
        const int lane = tid & 31;
        const float* xr = x + (long)row * DDIM;
        float s1 = 0.f, s2 = 0.f;
#pragma unroll
        for (int i = lane; i < DDIM; i += 32) {
            float xv = xr[i];
            s1 += xv * wlr[i];
            s2 += xv * wwd[i];
        }
#pragma unroll
        for (int o = 16; o; o >>= 1) {
            s1 += __shfl_xor_sync(0xffffffffu, s1, o);
            s2 += __shfl_xor_sync(0xffffffffu, s2, o);
        }
        if (!lane) { lrraw[row] = s1 + blr[0]; wdraw[row] = s2 + bwd[0]; }
        return;
    }
    __shared__ float tb[32][33];
    const int tx = tid & 31, ty = tid >> 5;
    if (bx < PB_T1) {
        const int u = bx - PB_ROW;
        const int z = u >> 6, b = u & 63;
        const int c0 = (b & 7) * 32, r0 = (b >> 3) * 32;
        const float* in = (z == 0) ? Wq : (z == 1) ? Wk : Wv;
        __half* out = WqkvT + (long)z * DDIM * DDIM;
#pragma unroll
        for (int k = 0; k < 4; k++)
            tb[ty + k * 8][tx] = in[(long)(r0 + ty + k * 8) * DDIM + c0 + tx];
        __syncthreads();
#pragma unroll
        for (int k = 0; k < 4; k++)
            out[(long)(c0 + ty + k * 8) * DDIM + r0 + tx] = __float2half_rn(tb[tx][ty + k * 8]);
        return;
    }
    if (bx < PB_T2) {
        const int u = bx - PB_T1;
        const int b = u >> 7, v = u & 127;
        const int c0 = (v & 15) * 32, r0 = (v >> 4) * 32;
        const float* in = W2 + (long)b * S_DH;
        __half* out = W2Th + (long)b * S_HD;
#pragma unroll
        for (int k = 0; k < 4; k++)
            tb[ty + k * 8][tx] = in[(long)(r0 + ty + k * 8) * HDIM + c0 + tx];
        __syncthreads();
#pragma unroll
        for (int k = 0; k < 4; k++)
            out[(long)(c0 + ty + k * 8) * DDIM + r0 + tx] = __float2half_rn(tb[tx][ty + k * 8]);
        return;
    }
    for (int j = tid; j < 768; j += 256)
        bqkv[j] = (j < 256) ? bq[j] : (j < 512) ? bk[j - 256] : bv[j - 512];
}

// ---------------- launch ----------------
extern "C" void kernel_launch(void* const* d_in, const int* in_sizes, int n_in,
                              void* d_out, int out_size)
{
    const float* x   = (const float*)d_in[0];
    const float* W1  = (const float*)d_in[1];
    const float* W2  = (const float*)d_in[2];
    const float* Wq  = (const float*)d_in[3];
    const float* bq  = (const float*)d_in[4];
    const float* Wk  = (const float*)d_in[5];
    const float* bk  = (const float*)d_in[6];
    const float* Wv  = (const float*)d_in[7];
    const float* bv  = (const float*)d_in[8];
    const float* wlr = (const float*)d_in[9];
    const float* blr = (const float*)d_in[10];
    const float* wwd = (const float*)d_in[11];
    const float* bwd = (const float*)d_in[12];
    const float* lbl = (const float*)d_in[13];
    const float* lbw = (const float*)d_in[14];

    float* Z2o = (float*)d_out;
    float* W1o = Z2o + (long)BATCH * LSEQ * DDIM;
    float* W2o = W1o + (long)BATCH * HDIM * DDIM;

    __half *xh, *WqkvT, *W1h, *W2h, *W2Th, *qkvh, *Z1h, *X2h, *gZ2h, *gZ1h, *X2nh, *Sh;
    float *bqkv, *qkvf, *Wsp1, *Wsp2;
    float *lrv, *cexp, *wfac, *clast, *lrraw, *wdraw;
    double* LcD;
    cudaGetSymbolAddress((void**)&xh,    g_xh);
    cudaGetSymbolAddress((void**)&WqkvT, g_WqkvT);
    cudaGetSymbolAddress((void**)&bqkv,  g_bqkv);
    cudaGetSymbolAddress((void**)&W1h,   g_W1h);
    cudaGetSymbolAddress((void**)&W2h,   g_W2h);
    cudaGetSymbolAddress((void**)&W2Th,  g_W2Th);
    cudaGetSymbolAddress((void**)&qkvf,  g_qkvf);
    cudaGetSymbolAddress((void**)&qkvh,  g_qkvh);
    cudaGetSymbolAddress((void**)&Z1h,   g_Z1h);
    cudaGetSymbolAddress((void**)&X2h,   g_X2h);
    cudaGetSymbolAddress((void**)&gZ2h,  g_gZ2h);
    cudaGetSymbolAddress((void**)&gZ1h,  g_gZ1h);
    cudaGetSymbolAddress((void**)&X2nh,  g_X2nh);
    cudaGetSymbolAddress((void**)&Sh,    g_Sh);
    cudaGetSymbolAddress((void**)&Wsp1,  g_Wsp1);
    cudaGetSymbolAddress((void**)&Wsp2,  g_Wsp2);
    cudaGetSymbolAddress((void**)&lrv,   g_lr);
    cudaGetSymbolAddress((void**)&LcD,   g_LcD);
    cudaGetSymbolAddress((void**)&cexp,  g_cexp);
    cudaGetSymbolAddress((void**)&wfac,  g_wfac);
    cudaGetSymbolAddress((void**)&clast, g_clast);
    cudaGetSymbolAddress((void**)&lrraw, g_lrraw);
    cudaGetSymbolAddress((void**)&wdraw, g_wdraw);

    cudaFuncSetAttribute(qkvscan_k,          cudaFuncAttributeMaxDynamicSharedMemorySize, SMEM_DYN);
    cudaFuncSetAttribute(hgemm_k<EPI_SILU2>, cudaFuncAttributeMaxDynamicSharedMemorySize, SMEM_DYN);
    cudaFuncSetAttribute(hgemm_k<EPI_G1>,    cudaFuncAttributeMaxDynamicSharedMemorySize, SMEM_DYN);
    cudaFuncSetAttribute(gzs1_k,             cudaFuncAttributeMaxDynamicSharedMemorySize, SMEM_DYN);
    cudaFuncSetAttribute(attn1wp_k,          cudaFuncAttributeMaxDynamicSharedMemorySize, SMEM_DYN);
    cudaFuncSetAttribute(s2_k,               cudaFuncAttributeMaxDynamicSharedMemorySize, SMEM_DYN);
    cudaFuncSetAttribute(attnred_k,          cudaFuncAttributeMaxDynamicSharedMemorySize, SMEM_DYN);

    dim3 blk(256);

    // 1: ALL prep
    prep_k<<<PB_ALL, 256>>>(x, xh, W1, W1h, W2, W2h, wlr, wwd, blr, bwd, lrraw, wdraw,
                            Wq, Wk, Wv, WqkvT, W2Th, bq, bk, bv, bqkv);

    // 2: QKV + scan
    qkvscan_k<<<dim3(7, 16, BATCH), blk, SMEM_DYN>>>(
        xh, WqkvT, qkvf, qkvh, bqkv,
        lrraw, wdraw, lbl, lbw, lrv, LcD, cexp, wfac, clast);

    // 3: Z1 (half) + X2 = silu(Z1)
    hgemm_k<EPI_SILU2><<<dim3(4, 16, BATCH), blk, SMEM_DYN>>>(
        qkvh + DDIM, S_L3D, L3D,  W1h, S_HD, DDIM,  Z1h, S_LH, HDIM,  DDIM,
        nullptr, 0, 0,  X2h, S_LH);

    // 4: gZ2 + S1-gen (merged)
    gzs1_k<<<dim3(63, 1, BATCH), blk, SMEM_DYN>>>(
        X2h, W2h, qkvf, gZ2h, qkvh, Sh, lrv, LcD);

    // 5: gZ1 = silu'(Z1) * (gZ2 @ W2)
    hgemm_k<EPI_G1><<<dim3(4, 16, BATCH), blk, SMEM_DYN>>>(
        gZ2h, S_LD, DDIM,  W2Th, S_HD, DDIM,  gZ1h, S_LH, HDIM,  DDIM,
        Z1h, S_LH, HDIM,  nullptr, 0);

    // 6: attn1 (fused, band 96) + W-next partials
    attn1wp_k<<<dim3(512, 1, 1), blk, SMEM_DYN>>>(
        qkvh, W1h, Sh, gZ1h, X2nh, cexp, gZ2h, X2h, Wsp1, Wsp2, wfac);

    // 7: S2-gen
    s2_k<<<dim3(124, 1, 1), blk, SMEM_DYN>>>(X2nh, X2h, Sh, lrv, LcD);

    // 8: attn2 (band 96) -> output + W-reduce filler
    attnred_k<<<dim3(128 + 1024, 1, 1), blk, SMEM_DYN>>>(
        X2nh, W2h, Sh, gZ2h, Z2o, cexp, Wsp1, W1, Wsp2, W2, clast, W1o, W2o);
}

// round 16
// speedup vs baseline: 1.3165x; 1.0237x over previous
#include <cuda_runtime.h>
#include <cuda_fp16.h>
#include <cstdint>

#define BATCH 4
#define LSEQ  2048
#define DDIM  256
#define HDIM  512
#define WBAND 64
#define NSPLIT 2
#define L3D   (3*DDIM)
#define BANDBACK 64   // attn band: k in [m0-BANDBACK, m0+128)

#define S_LD  ((long)LSEQ*DDIM)
#define S_LH  ((long)LSEQ*HDIM)
#define S_LL  ((long)LSEQ*LSEQ)
#define S_HD  ((long)HDIM*DDIM)
#define S_DH  ((long)DDIM*HDIM)
#define S_L3D ((long)LSEQ*L3D)

// ---------------- scratch ----------------
__device__ __half g_xh   [BATCH*LSEQ*DDIM];
__device__ __half g_WqkvT[3*DDIM*DDIM];
__device__ float  g_bqkv [3*DDIM];
__device__ __half g_W1h  [BATCH*HDIM*DDIM];
__device__ __half g_W2h  [BATCH*DDIM*HDIM];
__device__ __half g_W2Th [BATCH*HDIM*DDIM];
__device__ float  g_qkvf [BATCH*LSEQ*L3D];
__device__ __half g_qkvh [BATCH*LSEQ*L3D];
__device__ __half g_Z1h  [BATCH*LSEQ*HDIM];
__device__ __half g_X2h  [BATCH*LSEQ*HDIM];
__device__ __half g_gZ2h [BATCH*LSEQ*DDIM];
__device__ __half g_gZ1h [BATCH*LSEQ*HDIM];
__device__ __half g_X2nh [BATCH*LSEQ*HDIM];
__device__ __half g_Sh   [(size_t)BATCH*LSEQ*LSEQ];
__device__ float  g_Wsp1 [BATCH*NSPLIT*HDIM*DDIM];
__device__ float  g_Wsp2 [BATCH*NSPLIT*DDIM*HDIM];
__device__ float  g_lr   [BATCH*LSEQ];
__device__ double g_LcD  [BATCH*LSEQ];
__device__ float  g_cexp [BATCH*LSEQ];
__device__ float  g_wfac [BATCH*LSEQ];
__device__ float  g_clast[BATCH];
__device__ float  g_lrraw[BATCH*LSEQ];
__device__ float  g_wdraw[BATCH*LSEQ];

// ---------------- helpers ----------------
__device__ __forceinline__ uint32_t smem_u32(const void* p) {
    return (uint32_t)__cvta_generic_to_shared(p);
}
__device__ __forceinline__ float sigf(float x) {
    return __fdividef(1.0f, 1.0f + __expf(-x));
}
__device__ __forceinline__ void cpasync16(uint32_t dst, const void* src) {
    asm volatile("cp.async.cg.shared.global [%0], [%1], 16;\n" :: "r"(dst), "l"(src));
}
__device__ __forceinline__ void cp_commit() { asm volatile("cp.async.commit_group;\n" ::: "memory"); }
__device__ __forceinline__ void cp_wait1()  { asm volatile("cp.async.wait_group 1;\n" ::: "memory"); }
__device__ __forceinline__ void cp_wait0()  { asm volatile("cp.async.wait_group 0;\n" ::: "memory"); }
__device__ __forceinline__ void ldsm4(uint32_t& r0, uint32_t& r1, uint32_t& r2, uint32_t& r3, uint32_t a) {
    asm volatile("ldmatrix.sync.aligned.m8n8.x4.shared.b16 {%0,%1,%2,%3}, [%4];\n"
                 : "=r"(r0), "=r"(r1), "=r"(r2), "=r"(r3) : "r"(a));
}
__device__ __forceinline__ void ldsm4t(uint32_t& r0, uint32_t& r1, uint32_t& r2, uint32_t& r3, uint32_t a) {
    asm volatile("ldmatrix.sync.aligned.m8n8.x4.trans.shared.b16 {%0,%1,%2,%3}, [%4];\n"
                 : "=r"(r0), "=r"(r1), "=r"(r2), "=r"(r3) : "r"(a));
}
__device__ __forceinline__ void mma16816(float* d, const uint32_t* a, uint32_t b0, uint32_t b1) {
    asm volatile("mma.sync.aligned.m16n8k16.row.col.f32.f16.f16.f32 "
                 "{%0,%1,%2,%3}, {%4,%5,%6,%7}, {%8,%9}, {%0,%1,%2,%3};\n"
                 : "+f"(d[0]), "+f"(d[1]), "+f"(d[2]), "+f"(d[3])
                 : "r"(a[0]), "r"(a[1]), "r"(a[2]), "r"(a[3]), "r"(b0), "r"(b1));
}

#define SLOT     20480
#define SMEM_DYN (3 * SLOT)

// stage loaders
__device__ __forceinline__ void ld_mk(uint32_t dst, const __half* src, int ld, int r0, int k0, int tid) {
#pragma unroll
    for (int i = 0; i < 2; i++) {
        int c = i * 256 + tid, row = c >> 2, ch = c & 3;
        cpasync16(dst + row * 80 + ch * 16, src + (long)(r0 + row) * ld + k0 + ch * 8);
    }
}
__device__ __forceinline__ void ld_kn(uint32_t dst, const __half* src, int ld, int n0, int k0, int tid) {
#pragma unroll
    for (int i = 0; i < 2; i++) {
        int c = i * 256 + tid, k = c >> 4, ch = c & 15;
        cpasync16(dst + k * 272 + ch * 16, src + (long)(k0 + k) * ld + n0 + ch * 8);
    }
}
__device__ __forceinline__ void st_km_scaled(char* slotp, const __half* A, int lda, int m0, int k0,
                                             const float* wsc, int tid) {
    __half* smA = (__half*)slotp;
#pragma unroll
    for (int i = 0; i < 16; i++) {
        int e = i * 256 + tid, k = e >> 7, m = e & 127;
        smA[k * 136 + m] = __float2half_rn(__half2float(A[(long)(k0 + k) * lda + m0 + m]) * wsc[k0 + k]);
    }
}

// ---------------- fragment loaders ----------------
template<int TB>
__device__ __forceinline__ void ldB_frag(uint32_t bb, int ks, uint32_t (&Bp)[4][2], int lane, int wn) {
#pragma unroll
    for (int nj = 0; nj < 2; nj++) {
        uint32_t r0, r1, r2, r3;
        if (TB == 1) {
            uint32_t addr = bb + (uint32_t)((wn * 32 + nj * 16 + (lane & 15)) * 80
                                            + (ks * 16 + (lane >> 4) * 8) * 2);
            ldsm4(r0, r1, r2, r3, addr);
            Bp[nj*2][0] = r0; Bp[nj*2][1] = r2; Bp[nj*2+1][0] = r1; Bp[nj*2+1][1] = r3;
        } else {
            uint32_t addr = bb + (uint32_t)((ks * 16 + (lane & 15)) * 272
                                            + (wn * 32 + nj * 16 + (lane >> 4) * 8) * 2);
            ldsm4t(r0, r1, r2, r3, addr);
            Bp[nj*2][0] = r0; Bp[nj*2][1] = r1; Bp[nj*2+1][0] = r2; Bp[nj*2+1][1] = r3;
        }
    }
}
template<int TA>
__device__ __forceinline__ void ldA_frag(uint32_t ab, int ks, int mi, uint32_t (&Af)[4], int lane, int wm) {
    if (TA == 0) {
        uint32_t addr = ab + (uint32_t)((wm * 64 + mi * 16 + (lane & 15)) * 80
                                        + (ks * 16 + (lane >> 4) * 8) * 2);
        ldsm4(Af[0], Af[1], Af[2], Af[3], addr);
    } else {
        uint32_t addr = ab + (uint32_t)((ks * 16 + (lane & 7) + ((lane >> 4) << 3)) * 272
                                        + (wm * 64 + mi * 16 + ((lane >> 3) & 1) * 8) * 2);
        ldsm4t(Af[0], Af[1], Af[2], Af[3], addr);
    }
}

template<int TA, int TB>
__device__ __forceinline__ void compute_tile(uint32_t ab, uint32_t bb,
                                             float (&acc)[4][4][4], int lane, int wm, int wn)
{
    uint32_t Bp[2][4][2];
    uint32_t Af[2][4];
    ldB_frag<TB>(bb, 0, Bp[0], lane, wn);
    ldA_frag<TA>(ab, 0, 0, Af[0], lane, wm);
    ldB_frag<TB>(bb, 1, Bp[1], lane, wn);
#pragma unroll
    for (int ks = 0; ks < 2; ks++) {
#pragma unroll
        for (int mi = 0; mi < 4; mi++) {
            if (mi < 3)       ldA_frag<TA>(ab, ks, mi + 1, Af[(mi + 1) & 1], lane, wm);
            else if (ks == 0) ldA_frag<TA>(ab, 1, 0,      Af[0],            lane, wm);
#pragma unroll
            for (int ni = 0; ni < 4; ni++)
                mma16816(acc[mi][ni], Af[mi & 1], Bp[ks][ni][0], Bp[ks][ni][1]);
        }
    }
}

// full mainloop
template<int TB>
__device__ __forceinline__ void gemm_loop(uint32_t sb,
                                          const __half* A, int lda, int m0,
                                          const __half* B, int ldb, int n0,
                                          int kbeg, int kend, float (&acc)[4][4][4],
                                          int tid, int lane, int wm, int wn)
{
    const int nkt = (kend - kbeg) >> 5;
    ld_mk(sb, A, lda, m0, kbeg, tid);
    if (TB == 1) ld_mk(sb + 10240, B, ldb, n0, kbeg, tid);
    else         ld_kn(sb + 10240, B, ldb, n0, kbeg, tid);
    cp_commit();
    if (nkt > 1) {
        ld_mk(sb + SLOT, A, lda, m0, kbeg + 32, tid);
        if (TB == 1) ld_mk(sb + SLOT + 10240, B, ldb, n0, kbeg + 32, tid);
        else         ld_kn(sb + SLOT + 10240, B, ldb, n0, kbeg + 32, tid);
    }
    cp_commit();
    for (int kt = 0; kt < nkt; kt++) {
        cp_wait1(); __syncthreads();
        if (kt + 2 < nkt) {
            int sl = (kt + 2) % 3;
            int k0 = kbeg + (kt + 2) * 32;
            ld_mk(sb + sl * SLOT, A, lda, m0, k0, tid);
            if (TB == 1) ld_mk(sb + sl * SLOT + 10240, B, ldb, n0, k0, tid);
            else         ld_kn(sb + sl * SLOT + 10240, B, ldb, n0, k0, tid);
        }
        cp_commit();
        uint32_t ab = sb + (uint32_t)(kt % 3) * SLOT;
        compute_tile<0, TB>(ab, ab + 10240, acc, lane, wm, wn);
    }
}

// negated masked-decay S epilogue
__device__ __forceinline__ void s_epilogue(float (&acc)[4][4][4], __half* ShB,
                                           int m0, int n0,
                                           const float* lrv, const double* LcD,
                                           float* sFr, float* sFc,
                                           int tid, int lane, int wm, int wn)
{
    const int g = lane >> 2, t4 = lane & 3;
    if (tid < 128) sFr[tid] = __expf((float)(LcD[m0 + tid] - LcD[m0]));
    else { int i = tid - 128; sFc[i] = __expf((float)(LcD[m0] - LcD[n0 + i])) * lrv[n0 + i]; }
    __syncthreads();
#pragma unroll
    for (int mi = 0; mi < 4; mi++)
#pragma unroll
    for (int hf = 0; hf < 2; hf++) {
        const int r = m0 + wm * 64 + mi * 16 + g + hf * 8;
        const float f1 = sFr[r - m0];
#pragma unroll
        for (int ni = 0; ni < 4; ni++) {
            const int cc = n0 + wn * 32 + ni * 8 + t4 * 2;
            const int cl = wn * 32 + ni * 8 + t4 * 2;
            float v0 = acc[mi][ni][hf * 2], v1 = acc[mi][ni][hf * 2 + 1];
            float o0 = (cc     <= r) ? -(v0 * f1 * sFc[cl])     : 0.f;
            float o1 = (cc + 1 <= r) ? -(v1 * f1 * sFc[cl + 1]) : 0.f;
            *(__half2*)&ShB[(long)r * LSEQ + cc] = __floats2half2_rn(o0, o1);
        }
    }
}

// ---------------- QKV GEMM + scan merged ----------------
__global__ void __launch_bounds__(256, 2) qkvscan_k(
    const __half* __restrict__ xh, const __half* __restrict__ WqkvT,
    float* __restrict__ qkvf, __half* __restrict__ qkvh,
    const float* __restrict__ bqkv,
    const float* __restrict__ lrraw, const float* __restrict__ wdraw,
    const float* __restrict__ lbl, const float* __restrict__ lbw,
    float* __restrict__ lr, double* __restrict__ LcD,
    float* __restrict__ cexp, float* __restrict__ wfac,
    float* __restrict__ clast)
{
    const int tid = threadIdx.x;
    if (blockIdx.x == 6) {
        if (blockIdx.y != 0) return;
        const int b = blockIdx.z;
        __shared__ double ssum[256];
        __shared__ double sLast;
        const float ewd = expf(lbw[0]);
        const float elr = expf(lbl[0]);
        double loc[8];
        double tot = 0.0;
        const int base = b * LSEQ + tid * 8;
#pragma unroll
        for (int i = 0; i < 8; i++) {
            float sig = 1.f / (1.f + expf(-wdraw[base + i]));
            double lw = log(1.0 - (double)ewd * (double)sig);
            tot += lw;
            loc[i] = tot;
        }
        ssum[tid] = tot;
        __syncthreads();
        for (int off = 1; off < 256; off <<= 1) {
            double v = (tid >= off) ? ssum[tid - off] : 0.0;
            __syncthreads();
            ssum[tid] += v;
            __syncthreads();
        }
        double excl = (tid == 0) ? 0.0 : ssum[tid - 1];
        if (tid == 255) sLast = ssum[255];
        __syncthreads();
        double last = sLast;
#pragma unroll
        for (int i = 0; i < 8; i++) {
            double Lc = excl + loc[i];
            LcD[base + i] = Lc;
            cexp[base + i] = (float)exp(Lc);
            float l_r = elr / (1.f + expf(-lrraw[base + i]));
            lr[base + i] = l_r;
            wfac[base + i] = (float)((double)l_r * exp(last - Lc));
        }
        if (tid == 0) clast[b] = (float)exp(last);
        return;
    }

    const int bz = blockIdx.z;
    const int m0 = blockIdx.y * 128, n0 = blockIdx.x * 128;
    const __half* A = xh + bz * S_LD;
    float*  Cf = qkvf + bz * S_L3D;
    __half* Ch = qkvh + bz * S_L3D;

    extern __shared__ __align__(16) char dynsm[];
    const uint32_t sb = smem_u32(dynsm);
    const int w = tid >> 5, lane = tid & 31;
    const int wm = w >> 2, wn = w & 3, g = lane >> 2, t4 = lane & 3;

    float acc[4][4][4] = {};
    gemm_loop<1>(sb, A, DDIM, m0, WqkvT, DDIM, n0, 0, DDIM, acc, tid, lane, wm, wn);

#pragma unroll
    for (int mi = 0; mi < 4; mi++)
#pragma unroll
    for (int hf = 0; hf < 2; hf++) {
        const int r = m0 + wm * 64 + mi * 16 + g + hf * 8;
#pragma unroll
        for (int ni = 0; ni < 4; ni++) {
            const int cc = n0 + wn * 32 + ni * 8 + t4 * 2;
            float v0 = acc[mi][ni][hf * 2 + 0], v1 = acc[mi][ni][hf * 2 + 1];
            float o0 = v0 + bqkv[cc], o1 = v1 + bqkv[cc + 1];
            if (cc < 512)
                *(__half2*)&Ch[(long)r * L3D + cc] = __floats2half2_rn(o0, o1);
            else
                *(float2*)&Cf[(long)r * L3D + cc] = make_float2(o0, o1);
        }
    }
}

// ---------------- generic GEMM kernels ----------------
#define EPI_SILU2 3
#define EPI_G1    4

template<int EPI>
__global__ void __launch_bounds__(256, 2) hgemm_k(
    const __half* __restrict__ A, long sA, int lda,
    const __half* __restrict__ B, long sB, int ldb,
    __half* __restrict__ C, long sC, int ldc, int K,
    const __half* __restrict__ aux, long sAux, int ldaux,
    __half* __restrict__ out2, long sOut2)
{
    const int bz = blockIdx.z;
    const int m0 = blockIdx.y * 128, n0 = blockIdx.x * 128;
    A += bz * sA; B += bz * sB;
    C += bz * sC;
    if (aux)  aux  += bz * sAux;
    if (out2) out2 += bz * sOut2;

    extern __shared__ __align__(16) char dynsm[];
    const uint32_t sb = smem_u32(dynsm);
    const int tid = threadIdx.x, w = tid >> 5, lane = tid & 31;
    const int wm = w >> 2, wn = w & 3, g = lane >> 2, t4 = lane & 3;

    float acc[4][4][4] = {};
    gemm_loop<1>(sb, A, lda, m0, B, ldb, n0, 0, K, acc, tid, lane, wm, wn);

#pragma unroll
    for (int mi = 0; mi < 4; mi++)
#pragma unroll
    for (int hf = 0; hf < 2; hf++) {
        const int r = m0 + wm * 64 + mi * 16 + g + hf * 8;
#pragma unroll
        for (int ni = 0; ni < 4; ni++) {
            const int cc = n0 + wn * 32 + ni * 8 + t4 * 2;
            float v0 = acc[mi][ni][hf * 2 + 0], v1 = acc[mi][ni][hf * 2 + 1];
            if (EPI == EPI_SILU2) {
                *(__half2*)&C[(long)r * ldc + cc] = __floats2half2_rn(v0, v1);
                *(__half2*)&out2[(long)r * ldc + cc] =
                    __floats2half2_rn(v0 * sigf(v0), v1 * sigf(v1));
            } else { // EPI_G1: aux = Z1 (half)
                __half2 a2 = *(const __half2*)&aux[(long)r * ldaux + cc];
                float ax = __half2float(__low2half(a2));
                float ay = __half2float(__high2half(a2));
                float s0 = sigf(ax), s1 = sigf(ay);
                float i0 = ax * s0, i1 = ay * s1;
                *(__half2*)&C[(long)r * ldc + cc] = __floats2half2_rn(
                    (i0 + s0 * (1.f - i0)) * v0, (i1 + s1 * (1.f - i1)) * v1);
            }
        }
    }
}

// ---------------- gZ2 (32 tiles) + S1-gen (31 tiles) merged per batch ----------------
__global__ void __launch_bounds__(256, 2) gzs1_k(
    const __half* __restrict__ X2h, const __half* __restrict__ W2h,
    const float* __restrict__ qkvf, __half* __restrict__ gZ2h,
    const __half* __restrict__ qkvh, __half* __restrict__ Sh,
    const float* __restrict__ lrv, const double* __restrict__ LcD)
{
    const int bz = blockIdx.z;
    const int t = blockIdx.x;
    extern __shared__ __align__(16) char dynsm[];
    const uint32_t sb = smem_u32(dynsm);
    __shared__ float sFr[128], sFc[128];
    const int tid = threadIdx.x, w = tid >> 5, lane = tid & 31;
    const int wm = w >> 2, wn = w & 3, g = lane >> 2, t4 = lane & 3;
    float acc[4][4][4] = {};

    if (t < 32) {
        const int m0 = (t >> 1) * 128, n0 = (t & 1) * 128;
        gemm_loop<1>(sb, X2h + bz * S_LH, HDIM, m0, W2h + bz * S_DH, HDIM, n0,
                     0, HDIM, acc, tid, lane, wm, wn);
        const float* Vf = qkvf + bz * S_L3D + 2 * DDIM;
        __half* C = gZ2h + bz * S_LD;
#pragma unroll
        for (int mi = 0; mi < 4; mi++)
#pragma unroll
        for (int hf = 0; hf < 2; hf++) {
            const int r = m0 + wm * 64 + mi * 16 + g + hf * 8;
#pragma unroll
            for (int ni = 0; ni < 4; ni++) {
                const int cc = n0 + wn * 32 + ni * 8 + t4 * 2;
                float2 a = *(const float2*)&Vf[(long)r * L3D + cc];
                *(__half2*)&C[(long)r * DDIM + cc] = __floats2half2_rn(
                    acc[mi][ni][hf * 2] - a.x, acc[mi][ni][hf * 2 + 1] - a.y);
            }
        }
        return;
    }
    const int tt = t - 32;
    const int mm = (tt < 16) ? tt : tt - 15;
    const int nn = (tt < 16) ? tt : tt - 16;
    const int m0 = mm * 128, n0 = nn * 128;
    gemm_loop<1>(sb, qkvh + bz * S_L3D, L3D, m0, qkvh + bz * S_L3D + DDIM, L3D, n0,
                 0, DDIM, acc, tid, lane, wm, wn);
    s_epilogue(acc, Sh + bz * S_LL, m0, n0,
               lrv + (long)bz * LSEQ, LcD + (long)bz * LSEQ, sFr, sFc, tid, lane, wm, wn);
}

// ---------------- attn1 (fused cross+band) + W1/W2-next partials merged ----------------
__global__ void __launch_bounds__(256, 2) attn1wp_k(
    const __half* __restrict__ qkvh, const __half* __restrict__ W1h,
    const __half* __restrict__ Sh, const __half* __restrict__ gZ1h,
    __half* __restrict__ X2nh, const float* __restrict__ cexp,
    const __half* __restrict__ gZ2h, const __half* __restrict__ X2h,
    float* __restrict__ Wsp1, float* __restrict__ Wsp2,
    const float* __restrict__ wfac)
{
    extern __shared__ __align__(16) char dynsm[];
    const uint32_t sb = smem_u32(dynsm);
    const int tid = threadIdx.x, w = tid >> 5, lane = tid & 31;
    const int wm = w >> 2, wn = w & 3, g = lane >> 2, t4 = lane & 3;
    float acc[4][4][4] = {};
    const int x = blockIdx.x;

    if (x < 256) {
        const int bz = x >> 6, rem = x & 63;
        const int m0 = (rem >> 2) * 128, n0 = (rem & 3) * 128;
        const __half* Q = qkvh + bz * S_L3D;
        const float* ce = cexp + (long)bz * LSEQ;
        if (ce[m0] >= 1e-30f) {
            gemm_loop<1>(sb, Q, L3D, m0, W1h + bz * S_HD, DDIM, n0,
                         0, DDIM, acc, tid, lane, wm, wn);
#pragma unroll
            for (int mi = 0; mi < 4; mi++)
#pragma unroll
            for (int hf = 0; hf < 2; hf++) {
                const float s = ce[m0 + wm * 64 + mi * 16 + g + hf * 8];
#pragma unroll
                for (int ni = 0; ni < 4; ni++) {
                    acc[mi][ni][hf * 2 + 0] *= s;
                    acc[mi][ni][hf * 2 + 1] *= s;
                }
            }
            cp_wait0(); __syncthreads();
        }
        const int kbeg = (m0 >= 128) ? m0 - BANDBACK : 0;
        gemm_loop<0>(sb, Sh + bz * S_LL, LSEQ, m0, gZ1h + bz * S_LH, HDIM, n0,
                     kbeg, m0 + 128, acc, tid, lane, wm, wn);
        __half* C = X2nh + bz * S_LH;
#pragma unroll
        for (int mi = 0; mi < 4; mi++)
#pragma unroll
        for (int hf = 0; hf < 2; hf++) {
            const int r = m0 + wm * 64 + mi * 16 + g + hf * 8;
#pragma unroll
            for (int ni = 0; ni < 4; ni++) {
                const int cc = n0 + wn * 32 + ni * 8 + t4 * 2;
                float v0 = acc[mi][ni][hf * 2], v1 = acc[mi][ni][hf * 2 + 1];
                *(__half2*)&C[(long)r * HDIM + cc] =
                    __floats2half2_rn(v0 * sigf(v0), v1 * sigf(v1));
            }
        }
        return;
    }

    // W-next split-K partials (1 k-tile each, last WBAND=64 rows, NSPLIT=2)
    const int u = x - 256;                 // 0..127
    const bool isW2 = (u >= 64);
    const int v = u & 63;                  // 0..63
    const int z = v >> 3;                  // 0..7 = bz*NSPLIT+sp
    const int tile = v & 7;
    const int bz = z >> 1, sp = z & 1;
    int m0, n0, lda, ldb, ldc;
    const __half *A, *B; float* C;
    if (!isW2) {
        m0 = (tile >> 1) * 128; n0 = (tile & 1) * 128;
        A = gZ1h + bz * S_LH + (long)(LSEQ - WBAND) * HDIM; lda = HDIM;
        B = qkvh + bz * S_L3D + (long)(LSEQ - WBAND) * L3D + DDIM; ldb = L3D;
        C = Wsp1 + (long)z * S_HD; ldc = DDIM;
    } else {
        m0 = (tile >> 2) * 128; n0 = (tile & 3) * 128;
        A = gZ2h + bz * S_LD + (long)(LSEQ - WBAND) * DDIM; lda = DDIM;
        B = X2h + bz * S_LH + (long)(LSEQ - WBAND) * HDIM; ldb = HDIM;
        C = Wsp2 + (long)z * S_DH; ldc = HDIM;
    }
    const float* wsc = wfac + (long)bz * LSEQ + (LSEQ - WBAND);
    const int k0 = sp * 32;
    st_km_scaled(dynsm, A, lda, m0, k0, wsc, tid);
    ld_kn(sb + 10240, B, ldb, n0, k0, tid);
    cp_commit(); cp_wait0();
    __syncthreads();
    compute_tile<1, 0>(sb, sb + 10240, acc, lane, wm, wn);
#pragma unroll
    for (int mi = 0; mi < 4; mi++)
#pragma unroll
    for (int hf = 0; hf < 2; hf++) {
        const int r = m0 + wm * 64 + mi * 16 + g + hf * 8;
#pragma unroll
        for (int ni = 0; ni < 4; ni++) {
            const int cc = n0 + wn * 32 + ni * 8 + t4 * 2;
            *(float2*)&C[(long)r * ldc + cc] =
                make_float2(acc[mi][ni][hf * 2], acc[mi][ni][hf * 2 + 1]);
        }
    }
}

// ---------------- S2-gen ----------------
__global__ void __launch_bounds__(256, 2) s2_k(
    const __half* __restrict__ X2nh, const __half* __restrict__ X2h,
    __half* __restrict__ Sh, const float* __restrict__ lrv,
    const double* __restrict__ LcD)
{
    const int t = blockIdx.x;
    const int bz = t / 31, tt = t - bz * 31;
    const int mm = (tt < 16) ? tt : tt - 15;
    const int nn = (tt < 16) ? tt : tt - 16;
    const int m0 = mm * 128, n0 = nn * 128;

    extern __shared__ __align__(16) char dynsm[];
    const uint32_t sb = smem_u32(dynsm);
    __shared__ float sFr[128], sFc[128];
    const int tid = threadIdx.x, w = tid >> 5, lane = tid & 31;
    const int wm = w >> 2, wn = w & 3;
    float acc[4][4][4] = {};

    gemm_loop<1>(sb, X2nh + bz * S_LH, HDIM, m0, X2h + bz * S_LH, HDIM, n0,
                 0, HDIM, acc, tid, lane, wm, wn);
    s_epilogue(acc, Sh + (long)bz * S_LL, m0, n0,
               lrv + (long)bz * LSEQ, LcD + (long)bz * LSEQ, sFr, sFc, tid, lane, wm, wn);
}

// ---------------- attn2 (-> output, first) + W-reduce (filler) merged ----------------
__global__ void __launch_bounds__(256, 2) attnred_k(
    const __half* __restrict__ X2nh, const __half* __restrict__ W2h,
    const __half* __restrict__ Sh, const __half* __restrict__ gZ2h,
    float* __restrict__ Z2o, const float* __restrict__ cexp,
    const float* __restrict__ Wsp1, const float* __restrict__ W1,
    const float* __restrict__ Wsp2, const float* __restrict__ W2,
    const float* __restrict__ clast,
    float* __restrict__ W1o, float* __restrict__ W2o)
{
    const int x = blockIdx.x;
    const int tid = threadIdx.x;

    if (x >= 128) {
        const int u = x - 128;
        const int sel = u >> 9, rem = u & 511;
        const int b = rem >> 7, blk = rem & 127;
        const float *P = sel ? Wsp2 : Wsp1, *W = sel ? W2 : W1;
        float* out = sel ? W2o : W1o;
        const long MN = S_HD;
        const int idx = blk * 256 + tid;
        const float4* Pb = (const float4*)(P + (long)b * NSPLIT * MN);
        float4 s = make_float4(0.f, 0.f, 0.f, 0.f);
#pragma unroll
        for (int sp = 0; sp < NSPLIT; sp++) {
            float4 v = Pb[(long)sp * (MN >> 2) + idx];
            s.x += v.x; s.y += v.y; s.z += v.z; s.w += v.w;
        }
        const float c = clast[b];
        float4 wv = ((const float4*)(W + (long)b * MN))[idx];
        ((float4*)(out + (long)b * MN))[idx] =
            make_float4(c * wv.x - s.x, c * wv.y - s.y, c * wv.z - s.z, c * wv.w - s.w);
        return;
    }

    const int bz = x >> 5, rem = x & 31;
    const int m0 = (rem >> 1) * 128, n0 = (rem & 1) * 128;
    extern __shared__ __align__(16) char dynsm[];
    const uint32_t sb = smem_u32(dynsm);
    const int w = tid >> 5, lane = tid & 31;
    const int wm = w >> 2, wn = w & 3, g = lane >> 2, t4 = lane & 3;
    float acc[4][4][4] = {};
    const float* ce = cexp + (long)bz * LSEQ;

    if (ce[m0] >= 1e-30f) {
        gemm_loop<1>(sb, X2nh + bz * S_LH, HDIM, m0, W2h + bz * S_DH, HDIM, n0,
                     0, HDIM, acc, tid, lane, wm, wn);
#pragma unroll
        for (int mi = 0; mi < 4; mi++)
#pragma unroll
        for (int hf = 0; hf < 2; hf++) {
            const float s = ce[m0 + wm * 64 + mi * 16 + g + hf * 8];
#pragma unroll
            for (int ni = 0; ni < 4; ni++) {
                acc[mi][ni][hf * 2 + 0] *= s;
                acc[mi][ni][hf * 2 + 1] *= s;
            }
        }
        cp_wait0(); __syncthreads();
    }
    const int kbeg = (m0 >= 128) ? m0 - BANDBACK : 0;
    gemm_loop<0>(sb, Sh + (long)bz * S_LL, LSEQ, m0, gZ2h + bz * S_LD, DDIM, n0,
                 kbeg, m0 + 128, acc, tid, lane, wm, wn);
    float* C = Z2o + bz * S_LD;
#pragma unroll
    for (int mi = 0; mi < 4; mi++)
#pragma unroll
    for (int hf = 0; hf < 2; hf++) {
        const int r = m0 + wm * 64 + mi * 16 + g + hf * 8;
#pragma unroll
        for (int ni = 0; ni < 4; ni++) {
            const int cc = n0 + wn * 32 + ni * 8 + t4 * 2;
            *(float2*)&C[(long)r * DDIM + cc] =
                make_float2(acc[mi][ni][hf * 2], acc[mi][ni][hf * 2 + 1]);
        }
    }
}

// ---------------- single merged prep ----------------
#define CN1 ((long)BATCH*LSEQ*DDIM)
#define CN2 (CN1 + (long)BATCH*HDIM*DDIM)
#define CN3 (CN2 + (long)BATCH*DDIM*HDIM)
#define PB_CONV ((int)(CN3 / 1024))
#define PB_ROW  (PB_CONV + 1024)
#define PB_T1   (PB_ROW + 192)
#define PB_T2   (PB_T1 + 512)
#define PB_ALL  (PB_T2 + 1)
__global__ void prep_k(const float* __restrict__ x,  __half* __restrict__ xh,
                       const float* __restrict__ W1, __half* __restrict__ W1h,
                       const float* __restrict__ W2, __half* __restrict__ W2h,
                       const float* __restrict__ wlr, const float* __restrict__ wwd,
                       const float* __restrict__ blr, const float* __restrict__ bwd,
                       float* __restrict__ lrraw, float* __restrict__ wdraw,
                       const float* __restrict__ Wq, const float* __restrict__ Wk,
                       const float* __restrict__ Wv, __half* __restrict__ WqkvT,
                       __half* __restrict__ W2Th,
                       const float* __restrict__ bq, const float* __restrict__ bk,
                       const float* __restrict__ bv, float* __restrict__ bqkv)
{
    const int bx = blockIdx.x, tid = threadIdx.x;
    if (bx < PB_CONV) {
        const long e = (long)(bx * 256 + tid) * 4;
        const float* src; __half* dst; long off;
        if (e < CN1)      { src = x;  dst = xh;  off = e; }
        else if (e < CN2) { src = W1; dst = W1h; off = e - CN1; }
        else              { src = W2; dst = W2h; off = e - CN2; }
        float4 v = *(const float4*)(src + off);
        *(__half2*)(dst + off)     = __floats2half2_rn(v.x, v.y);
        *(__half2*)(dst + off + 2) = __floats2half2_rn(v.z, v.w);
        return;
    }
    if (bx < PB_ROW) {
        const int row = (bx - PB_CONV) * 8 + (tid >> 5);
        const int lane = tid & 31;
        const float* xr = x + (long)row * DDIM;
        float s1 = 0.f, s2 = 0.f;
#pragma unroll
        for (int i = lane; i < DDIM; i += 32) {
            float xv = xr[i];
            s1 += xv * wlr[i];
            s2 += xv * wwd[i];
        }
#pragma unroll
        for (int o = 16; o; o >>= 1) {
            s1 += __shfl_xor_sync(0xffffffffu, s1, o);
            s2 += __shfl_xor_sync(0xffffffffu, s2, o);
        }
        if (!lane) { lrraw[row] = s1 + blr[0]; wdraw[row] = s2 + bwd[0]; }
        return;
    }
    __shared__ float tb[32][33];
    const int tx = tid & 31, ty = tid >> 5;
    if (bx < PB_T1) {
        const int u = bx - PB_ROW;
        const int z = u >> 6, b = u & 63;
        const int c0 = (b & 7) * 32, r0 = (b >> 3) * 32;
        const float* in = (z == 0) ? Wq : (z == 1) ? Wk : Wv;
        __half* out = WqkvT + (long)z * DDIM * DDIM;
#pragma unroll
        for (int k = 0; k < 4; k++)
            tb[ty + k * 8][tx] = in[(long)(r0 + ty + k * 8) * DDIM + c0 + tx];
        __syncthreads();
#pragma unroll
        for (int k = 0; k < 4; k++)
            out[(long)(c0 + ty + k * 8) * DDIM + r0 + tx] = __float2half_rn(tb[tx][ty + k * 8]);
        return;
    }
    if (bx < PB_T2) {
        const int u = bx - PB_T1;
        const int b = u >> 7, v = u & 127;
        const int c0 = (v & 15) * 32, r0 = (v >> 4) * 32;
        const float* in = W2 + (long)b * S_DH;
        __half* out = W2Th + (long)b * S_HD;
#pragma unroll
        for (int k = 0; k < 4; k++)
            tb[ty + k * 8][tx] = in[(long)(r0 + ty + k * 8) * HDIM + c0 + tx];
        __syncthreads();
#pragma unroll
        for (int k = 0; k < 4; k++)
            out[(long)(c0 + ty + k * 8) * DDIM + r0 + tx] = __float2half_rn(tb[tx][ty + k * 8]);
        return;
    }
    for (int j = tid; j < 768; j += 256)
        bqkv[j] = (j < 256) ? bq[j] : (j < 512) ? bk[j - 256] : bv[j - 512];
}

// ---------------- launch ----------------
extern "C" void kernel_launch(void* const* d_in, const int* in_sizes, int n_in,
                              void* d_out, int out_size)
{
    const float* x   = (const float*)d_in[0];
    const float* W1  = (const float*)d_in[1];
    const float* W2  = (const float*)d_in[2];
    const float* Wq  = (const float*)d_in[3];
    const float* bq  = (const float*)d_in[4];
    const float* Wk  = (const float*)d_in[5];
    const float* bk  = (const float*)d_in[6];
    const float* Wv  = (const float*)d_in[7];
    const float* bv  = (const float*)d_in[8];
    const float* wlr = (const float*)d_in[9];
    const float* blr = (const float*)d_in[10];
    const float* wwd = (const float*)d_in[11];
    const float* bwd = (const float*)d_in[12];
    const float* lbl = (const float*)d_in[13];
    const float* lbw = (const float*)d_in[14];

    float* Z2o = (float*)d_out;
    float* W1o = Z2o + (long)BATCH * LSEQ * DDIM;
    float* W2o = W1o + (long)BATCH * HDIM * DDIM;

    __half *xh, *WqkvT, *W1h, *W2h, *W2Th, *qkvh, *Z1h, *X2h, *gZ2h, *gZ1h, *X2nh, *Sh;
    float *bqkv, *qkvf, *Wsp1, *Wsp2;
    float *lrv, *cexp, *wfac, *clast, *lrraw, *wdraw;
    double* LcD;
    cudaGetSymbolAddress((void**)&xh,    g_xh);
    cudaGetSymbolAddress((void**)&WqkvT, g_WqkvT);
    cudaGetSymbolAddress((void**)&bqkv,  g_bqkv);
    cudaGetSymbolAddress((void**)&W1h,   g_W1h);
    cudaGetSymbolAddress((void**)&W2h,   g_W2h);
    cudaGetSymbolAddress((void**)&W2Th,  g_W2Th);
    cudaGetSymbolAddress((void**)&qkvf,  g_qkvf);
    cudaGetSymbolAddress((void**)&qkvh,  g_qkvh);
    cudaGetSymbolAddress((void**)&Z1h,   g_Z1h);
    cudaGetSymbolAddress((void**)&X2h,   g_X2h);
    cudaGetSymbolAddress((void**)&gZ2h,  g_gZ2h);
    cudaGetSymbolAddress((void**)&gZ1h,  g_gZ1h);
    cudaGetSymbolAddress((void**)&X2nh,  g_X2nh);
    cudaGetSymbolAddress((void**)&Sh,    g_Sh);
    cudaGetSymbolAddress((void**)&Wsp1,  g_Wsp1);
    cudaGetSymbolAddress((void**)&Wsp2,  g_Wsp2);
    cudaGetSymbolAddress((void**)&lrv,   g_lr);
    cudaGetSymbolAddress((void**)&LcD,   g_LcD);
    cudaGetSymbolAddress((void**)&cexp,  g_cexp);
    cudaGetSymbolAddress((void**)&wfac,  g_wfac);
    cudaGetSymbolAddress((void**)&clast, g_clast);
    cudaGetSymbolAddress((void**)&lrraw, g_lrraw);
    cudaGetSymbolAddress((void**)&wdraw, g_wdraw);

    cudaFuncSetAttribute(qkvscan_k,          cudaFuncAttributeMaxDynamicSharedMemorySize, SMEM_DYN);
    cudaFuncSetAttribute(hgemm_k<EPI_SILU2>, cudaFuncAttributeMaxDynamicSharedMemorySize, SMEM_DYN);
    cudaFuncSetAttribute(hgemm_k<EPI_G1>,    cudaFuncAttributeMaxDynamicSharedMemorySize, SMEM_DYN);
    cudaFuncSetAttribute(gzs1_k,             cudaFuncAttributeMaxDynamicSharedMemorySize, SMEM_DYN);
    cudaFuncSetAttribute(attn1wp_k,          cudaFuncAttributeMaxDynamicSharedMemorySize, SMEM_DYN);
    cudaFuncSetAttribute(s2_k,               cudaFuncAttributeMaxDynamicSharedMemorySize, SMEM_DYN);
    cudaFuncSetAttribute(attnred_k,          cudaFuncAttributeMaxDynamicSharedMemorySize, SMEM_DYN);

    dim3 blk(256);

    // 1: ALL prep
    prep_k<<<PB_ALL, 256>>>(x, xh, W1, W1h, W2, W2h, wlr, wwd, blr, bwd, lrraw, wdraw,
                            Wq, Wk, Wv, WqkvT, W2Th, bq, bk, bv, bqkv);

    // 2: QKV + scan
    qkvscan_k<<<dim3(7, 16, BATCH), blk, SMEM_DYN>>>(
        xh, WqkvT, qkvf, qkvh, bqkv,
        lrraw, wdraw, lbl, lbw, lrv, LcD, cexp, wfac, clast);

    // 3: Z1 (half) + X2 = silu(Z1)
    hgemm_k<EPI_SILU2><<<dim3(4, 16, BATCH), blk, SMEM_DYN>>>(
        qkvh + DDIM, S_L3D, L3D,  W1h, S_HD, DDIM,  Z1h, S_LH, HDIM,  DDIM,
        nullptr, 0, 0,  X2h, S_LH);

    // 4: gZ2 + S1-gen (merged)
    gzs1_k<<<dim3(63, 1, BATCH), blk, SMEM_DYN>>>(
        X2h, W2h, qkvf, gZ2h, qkvh, Sh, lrv, LcD);

    // 5: gZ1 = silu'(Z1) * (gZ2 @ W2)
    hgemm_k<EPI_G1><<<dim3(4, 16, BATCH), blk, SMEM_DYN>>>(
        gZ2h, S_LD, DDIM,  W2Th, S_HD, DDIM,  gZ1h, S_LH, HDIM,  DDIM,
        Z1h, S_LH, HDIM,  nullptr, 0);

    // 6: attn1 (fused, band 64) + W-next partials (WBAND=64, NSPLIT=2)
    attn1wp_k<<<dim3(384, 1, 1), blk, SMEM_DYN>>>(
        qkvh, W1h, Sh, gZ1h, X2nh, cexp, gZ2h, X2h, Wsp1, Wsp2, wfac);

    // 7: S2-gen
    s2_k<<<dim3(124, 1, 1), blk, SMEM_DYN>>>(X2nh, X2h, Sh, lrv, LcD);

    // 8: attn2 (band 64) -> output + W-reduce filler
    attnred_k<<<dim3(128 + 1024, 1, 1), blk, SMEM_DYN>>>(
        X2nh, W2h, Sh, gZ2h, Z2o, cexp, Wsp1, W1, Wsp2, W2, clast, W1o, W2o);
}

// round 17
// speedup vs baseline: 1.3317x; 1.0116x over previous
#include <cuda_runtime.h>
#include <cuda_fp16.h>
#include <cstdint>

#define BATCH 4
#define LSEQ  2048
#define DDIM  256
#define HDIM  512
#define WBAND 64
#define NSPLIT 2
#define L3D   (3*DDIM)
#define BANDBACK 64
#define CSKIP_TH 1e-10f

#define S_LD  ((long)LSEQ*DDIM)
#define S_LH  ((long)LSEQ*HDIM)
#define S_LL  ((long)LSEQ*LSEQ)
#define S_HD  ((long)HDIM*DDIM)
#define S_DH  ((long)DDIM*HDIM)
#define S_L3D ((long)LSEQ*L3D)

// ---------------- scratch ----------------
__device__ __half g_xh   [BATCH*LSEQ*DDIM];
__device__ __half g_WqkvT[3*DDIM*DDIM];
__device__ float  g_bqkv [3*DDIM];
__device__ __half g_W1h  [BATCH*HDIM*DDIM];
__device__ __half g_W2h  [BATCH*DDIM*HDIM];
__device__ __half g_W2Th [BATCH*HDIM*DDIM];
__device__ __half g_qkvh [BATCH*LSEQ*L3D];   // Q,K,V all half, packed
__device__ __half g_Z1h  [BATCH*LSEQ*HDIM];
__device__ __half g_X2h  [BATCH*LSEQ*HDIM];
__device__ __half g_gZ2h [BATCH*LSEQ*DDIM];
__device__ __half g_gZ1h [BATCH*LSEQ*HDIM];
__device__ __half g_X2nh [BATCH*LSEQ*HDIM];
__device__ __half g_Sh   [(size_t)BATCH*LSEQ*LSEQ];
__device__ float  g_Wsp1 [BATCH*NSPLIT*HDIM*DDIM];
__device__ float  g_Wsp2 [BATCH*NSPLIT*DDIM*HDIM];
__device__ float  g_lr   [BATCH*LSEQ];
__device__ double g_LcD  [BATCH*LSEQ];
__device__ float  g_cexp [BATCH*LSEQ];
__device__ float  g_wfac [BATCH*LSEQ];
__device__ float  g_clast[BATCH];
__device__ float  g_lrraw[BATCH*LSEQ];
__device__ float  g_wdraw[BATCH*LSEQ];

// ---------------- helpers ----------------
__device__ __forceinline__ uint32_t smem_u32(const void* p) {
    return (uint32_t)__cvta_generic_to_shared(p);
}
__device__ __forceinline__ float sigf(float x) {
    return __fdividef(1.0f, 1.0f + __expf(-x));
}
__device__ __forceinline__ void cpasync16(uint32_t dst, const void* src) {
    asm volatile("cp.async.cg.shared.global [%0], [%1], 16;\n" :: "r"(dst), "l"(src));
}
__device__ __forceinline__ void cp_commit() { asm volatile("cp.async.commit_group;\n" ::: "memory"); }
__device__ __forceinline__ void cp_wait1()  { asm volatile("cp.async.wait_group 1;\n" ::: "memory"); }
__device__ __forceinline__ void cp_wait0()  { asm volatile("cp.async.wait_group 0;\n" ::: "memory"); }
__device__ __forceinline__ void ldsm4(uint32_t& r0, uint32_t& r1, uint32_t& r2, uint32_t& r3, uint32_t a) {
    asm volatile("ldmatrix.sync.aligned.m8n8.x4.shared.b16 {%0,%1,%2,%3}, [%4];\n"
                 : "=r"(r0), "=r"(r1), "=r"(r2), "=r"(r3) : "r"(a));
}
__device__ __forceinline__ void ldsm4t(uint32_t& r0, uint32_t& r1, uint32_t& r2, uint32_t& r3, uint32_t a) {
    asm volatile("ldmatrix.sync.aligned.m8n8.x4.trans.shared.b16 {%0,%1,%2,%3}, [%4];\n"
                 : "=r"(r0), "=r"(r1), "=r"(r2), "=r"(r3) : "r"(a));
}
__device__ __forceinline__ void mma16816(float* d, const uint32_t* a, uint32_t b0, uint32_t b1) {
    asm volatile("mma.sync.aligned.m16n8k16.row.col.f32.f16.f16.f32 "
                 "{%0,%1,%2,%3}, {%4,%5,%6,%7}, {%8,%9}, {%0,%1,%2,%3};\n"
                 : "+f"(d[0]), "+f"(d[1]), "+f"(d[2]), "+f"(d[3])
                 : "r"(a[0]), "r"(a[1]), "r"(a[2]), "r"(a[3]), "r"(b0), "r"(b1));
}

#define SLOT     20480
#define SMEM_DYN (3 * SLOT)

// stage loaders
__device__ __forceinline__ void ld_mk(uint32_t dst, const __half* src, int ld, int r0, int k0, int tid) {
#pragma unroll
    for (int i = 0; i < 2; i++) {
        int c = i * 256 + tid, row = c >> 2, ch = c & 3;
        cpasync16(dst + row * 80 + ch * 16, src + (long)(r0 + row) * ld + k0 + ch * 8);
    }
}
__device__ __forceinline__ void ld_kn(uint32_t dst, const __half* src, int ld, int n0, int k0, int tid) {
#pragma unroll
    for (int i = 0; i < 2; i++) {
        int c = i * 256 + tid, k = c >> 4, ch = c & 15;
        cpasync16(dst + k * 272 + ch * 16, src + (long)(k0 + k) * ld + n0 + ch * 8);
    }
}
__device__ __forceinline__ void st_km_scaled(char* slotp, const __half* A, int lda, int m0, int k0,
                                             const float* wsc, int tid) {
    __half* smA = (__half*)slotp;
#pragma unroll
    for (int i = 0; i < 16; i++) {
        int e = i * 256 + tid, k = e >> 7, m = e & 127;
        smA[k * 136 + m] = __float2half_rn(__half2float(A[(long)(k0 + k) * lda + m0 + m]) * wsc[k0 + k]);
    }
}

// ---------------- fragment loaders ----------------
template<int TB>
__device__ __forceinline__ void ldB_frag(uint32_t bb, int ks, uint32_t (&Bp)[4][2], int lane, int wn) {
#pragma unroll
    for (int nj = 0; nj < 2; nj++) {
        uint32_t r0, r1, r2, r3;
        if (TB == 1) {
            uint32_t addr = bb + (uint32_t)((wn * 32 + nj * 16 + (lane & 15)) * 80
                                            + (ks * 16 + (lane >> 4) * 8) * 2);
            ldsm4(r0, r1, r2, r3, addr);
            Bp[nj*2][0] = r0; Bp[nj*2][1] = r2; Bp[nj*2+1][0] = r1; Bp[nj*2+1][1] = r3;
        } else {
            uint32_t addr = bb + (uint32_t)((ks * 16 + (lane & 15)) * 272
                                            + (wn * 32 + nj * 16 + (lane >> 4) * 8) * 2);
            ldsm4t(r0, r1, r2, r3, addr);
            Bp[nj*2][0] = r0; Bp[nj*2][1] = r1; Bp[nj*2+1][0] = r2; Bp[nj*2+1][1] = r3;
        }
    }
}
template<int TA>
__device__ __forceinline__ void ldA_frag(uint32_t ab, int ks, int mi, uint32_t (&Af)[4], int lane, int wm) {
    if (TA == 0) {
        uint32_t addr = ab + (uint32_t)((wm * 64 + mi * 16 + (lane & 15)) * 80
                                        + (ks * 16 + (lane >> 4) * 8) * 2);
        ldsm4(Af[0], Af[1], Af[2], Af[3], addr);
    } else {
        uint32_t addr = ab + (uint32_t)((ks * 16 + (lane & 7) + ((lane >> 4) << 3)) * 272
                                        + (wm * 64 + mi * 16 + ((lane >> 3) & 1) * 8) * 2);
        ldsm4t(Af[0], Af[1], Af[2], Af[3], addr);
    }
}

template<int TA, int TB>
__device__ __forceinline__ void compute_tile(uint32_t ab, uint32_t bb,
                                             float (&acc)[4][4][4], int lane, int wm, int wn)
{
    uint32_t Bp[2][4][2];
    uint32_t Af[2][4];
    ldB_frag<TB>(bb, 0, Bp[0], lane, wn);
    ldA_frag<TA>(ab, 0, 0, Af[0], lane, wm);
    ldB_frag<TB>(bb, 1, Bp[1], lane, wn);
#pragma unroll
    for (int ks = 0; ks < 2; ks++) {
#pragma unroll
        for (int mi = 0; mi < 4; mi++) {
            if (mi < 3)       ldA_frag<TA>(ab, ks, mi + 1, Af[(mi + 1) & 1], lane, wm);
            else if (ks == 0) ldA_frag<TA>(ab, 1, 0,      Af[0],            lane, wm);
#pragma unroll
            for (int ni = 0; ni < 4; ni++)
                mma16816(acc[mi][ni], Af[mi & 1], Bp[ks][ni][0], Bp[ks][ni][1]);
        }
    }
}

// full mainloop
template<int TB>
__device__ __forceinline__ void gemm_loop(uint32_t sb,
                                          const __half* A, int lda, int m0,
                                          const __half* B, int ldb, int n0,
                                          int kbeg, int kend, float (&acc)[4][4][4],
                                          int tid, int lane, int wm, int wn)
{
    const int nkt = (kend - kbeg) >> 5;
    ld_mk(sb, A, lda, m0, kbeg, tid);
    if (TB == 1) ld_mk(sb + 10240, B, ldb, n0, kbeg, tid);
    else         ld_kn(sb + 10240, B, ldb, n0, kbeg, tid);
    cp_commit();
    if (nkt > 1) {
        ld_mk(sb + SLOT, A, lda, m0, kbeg + 32, tid);
        if (TB == 1) ld_mk(sb + SLOT + 10240, B, ldb, n0, kbeg + 32, tid);
        else         ld_kn(sb + SLOT + 10240, B, ldb, n0, kbeg + 32, tid);
    }
    cp_commit();
    for (int kt = 0; kt < nkt; kt++) {
        cp_wait1(); __syncthreads();
        if (kt + 2 < nkt) {
            int sl = (kt + 2) % 3;
            int k0 = kbeg + (kt + 2) * 32;
            ld_mk(sb + sl * SLOT, A, lda, m0, k0, tid);
            if (TB == 1) ld_mk(sb + sl * SLOT + 10240, B, ldb, n0, k0, tid);
            else         ld_kn(sb + sl * SLOT + 10240, B, ldb, n0, k0, tid);
        }
        cp_commit();
        uint32_t ab = sb + (uint32_t)(kt % 3) * SLOT;
        compute_tile<0, TB>(ab, ab + 10240, acc, lane, wm, wn);
    }
}

// negated masked-decay S epilogue
__device__ __forceinline__ void s_epilogue(float (&acc)[4][4][4], __half* ShB,
                                           int m0, int n0,
                                           const float* lrv, const double* LcD,
                                           float* sFr, float* sFc,
                                           int tid, int lane, int wm, int wn)
{
    const int g = lane >> 2, t4 = lane & 3;
    if (tid < 128) sFr[tid] = __expf((float)(LcD[m0 + tid] - LcD[m0]));
    else { int i = tid - 128; sFc[i] = __expf((float)(LcD[m0] - LcD[n0 + i])) * lrv[n0 + i]; }
    __syncthreads();
#pragma unroll
    for (int mi = 0; mi < 4; mi++)
#pragma unroll
    for (int hf = 0; hf < 2; hf++) {
        const int r = m0 + wm * 64 + mi * 16 + g + hf * 8;
        const float f1 = sFr[r - m0];
#pragma unroll
        for (int ni = 0; ni < 4; ni++) {
            const int cc = n0 + wn * 32 + ni * 8 + t4 * 2;
            const int cl = wn * 32 + ni * 8 + t4 * 2;
            float v0 = acc[mi][ni][hf * 2], v1 = acc[mi][ni][hf * 2 + 1];
            float o0 = (cc     <= r) ? -(v0 * f1 * sFc[cl])     : 0.f;
            float o1 = (cc + 1 <= r) ? -(v1 * f1 * sFc[cl + 1]) : 0.f;
            *(__half2*)&ShB[(long)r * LSEQ + cc] = __floats2half2_rn(o0, o1);
        }
    }
}

// ---------------- QKV GEMM (all-half output) + scan merged ----------------
__global__ void __launch_bounds__(256, 2) qkvscan_k(
    const __half* __restrict__ xh, const __half* __restrict__ WqkvT,
    __half* __restrict__ qkvh,
    const float* __restrict__ bqkv,
    const float* __restrict__ lrraw, const float* __restrict__ wdraw,
    const float* __restrict__ lbl, const float* __restrict__ lbw,
    float* __restrict__ lr, double* __restrict__ LcD,
    float* __restrict__ cexp, float* __restrict__ wfac,
    float* __restrict__ clast)
{
    const int tid = threadIdx.x;
    if (blockIdx.x == 6) {
        if (blockIdx.y != 0) return;
        const int b = blockIdx.z;
        __shared__ double ssum[256];
        __shared__ double sLast;
        const float ewd = expf(lbw[0]);
        const float elr = expf(lbl[0]);
        double loc[8];
        double tot = 0.0;
        const int base = b * LSEQ + tid * 8;
#pragma unroll
        for (int i = 0; i < 8; i++) {
            float sig = 1.f / (1.f + expf(-wdraw[base + i]));
            double lw = log(1.0 - (double)ewd * (double)sig);
            tot += lw;
            loc[i] = tot;
        }
        ssum[tid] = tot;
        __syncthreads();
        for (int off = 1; off < 256; off <<= 1) {
            double v = (tid >= off) ? ssum[tid - off] : 0.0;
            __syncthreads();
            ssum[tid] += v;
            __syncthreads();
        }
        double excl = (tid == 0) ? 0.0 : ssum[tid - 1];
        if (tid == 255) sLast = ssum[255];
        __syncthreads();
        double last = sLast;
#pragma unroll
        for (int i = 0; i < 8; i++) {
            double Lc = excl + loc[i];
            LcD[base + i] = Lc;
            cexp[base + i] = (float)exp(Lc);
            float l_r = elr / (1.f + expf(-lrraw[base + i]));
            lr[base + i] = l_r;
            wfac[base + i] = (float)((double)l_r * exp(last - Lc));
        }
        if (tid == 0) clast[b] = (float)exp(last);
        return;
    }

    const int bz = blockIdx.z;
    const int m0 = blockIdx.y * 128, n0 = blockIdx.x * 128;
    const __half* A = xh + bz * S_LD;
    __half* Ch = qkvh + bz * S_L3D;

    extern __shared__ __align__(16) char dynsm[];
    const uint32_t sb = smem_u32(dynsm);
    const int w = tid >> 5, lane = tid & 31;
    const int wm = w >> 2, wn = w & 3, g = lane >> 2, t4 = lane & 3;

    float acc[4][4][4] = {};
    gemm_loop<1>(sb, A, DDIM, m0, WqkvT, DDIM, n0, 0, DDIM, acc, tid, lane, wm, wn);

#pragma unroll
    for (int mi = 0; mi < 4; mi++)
#pragma unroll
    for (int hf = 0; hf < 2; hf++) {
        const int r = m0 + wm * 64 + mi * 16 + g + hf * 8;
#pragma unroll
        for (int ni = 0; ni < 4; ni++) {
            const int cc = n0 + wn * 32 + ni * 8 + t4 * 2;
            float v0 = acc[mi][ni][hf * 2 + 0], v1 = acc[mi][ni][hf * 2 + 1];
            *(__half2*)&Ch[(long)r * L3D + cc] =
                __floats2half2_rn(v0 + bqkv[cc], v1 + bqkv[cc + 1]);
        }
    }
}

// ---------------- generic GEMM kernels ----------------
#define EPI_SILU2 3
#define EPI_G1    4

template<int EPI>
__global__ void __launch_bounds__(256, 2) hgemm_k(
    const __half* __restrict__ A, long sA, int lda,
    const __half* __restrict__ B, long sB, int ldb,
    __half* __restrict__ C, long sC, int ldc, int K,
    const __half* __restrict__ aux, long sAux, int ldaux,
    __half* __restrict__ out2, long sOut2)
{
    const int bz = blockIdx.z;
    const int m0 = blockIdx.y * 128, n0 = blockIdx.x * 128;
    A += bz * sA; B += bz * sB;
    C += bz * sC;
    if (aux)  aux  += bz * sAux;
    if (out2) out2 += bz * sOut2;

    extern __shared__ __align__(16) char dynsm[];
    const uint32_t sb = smem_u32(dynsm);
    const int tid = threadIdx.x, w = tid >> 5, lane = tid & 31;
    const int wm = w >> 2, wn = w & 3, g = lane >> 2, t4 = lane & 3;

    float acc[4][4][4] = {};
    gemm_loop<1>(sb, A, lda, m0, B, ldb, n0, 0, K, acc, tid, lane, wm, wn);

#pragma unroll
    for (int mi = 0; mi < 4; mi++)
#pragma unroll
    for (int hf = 0; hf < 2; hf++) {
        const int r = m0 + wm * 64 + mi * 16 + g + hf * 8;
#pragma unroll
        for (int ni = 0; ni < 4; ni++) {
            const int cc = n0 + wn * 32 + ni * 8 + t4 * 2;
            float v0 = acc[mi][ni][hf * 2 + 0], v1 = acc[mi][ni][hf * 2 + 1];
            if (EPI == EPI_SILU2) {
                *(__half2*)&C[(long)r * ldc + cc] = __floats2half2_rn(v0, v1);
                *(__half2*)&out2[(long)r * ldc + cc] =
                    __floats2half2_rn(v0 * sigf(v0), v1 * sigf(v1));
            } else { // EPI_G1: aux = Z1 (half)
                __half2 a2 = *(const __half2*)&aux[(long)r * ldaux + cc];
                float ax = __half2float(__low2half(a2));
                float ay = __half2float(__high2half(a2));
                float s0 = sigf(ax), s1 = sigf(ay);
                float i0 = ax * s0, i1 = ay * s1;
                *(__half2*)&C[(long)r * ldc + cc] = __floats2half2_rn(
                    (i0 + s0 * (1.f - i0)) * v0, (i1 + s1 * (1.f - i1)) * v1);
            }
        }
    }
}

// ---------------- gZ2 (32 tiles) + S1-gen (31 tiles) merged per batch ----------------
__global__ void __launch_bounds__(256, 2) gzs1_k(
    const __half* __restrict__ X2h, const __half* __restrict__ W2h,
    const __half* __restrict__ qkvh, __half* __restrict__ gZ2h,
    __half* __restrict__ Sh,
    const float* __restrict__ lrv, const double* __restrict__ LcD)
{
    const int bz = blockIdx.z;
    const int t = blockIdx.x;
    extern __shared__ __align__(16) char dynsm[];
    const uint32_t sb = smem_u32(dynsm);
    __shared__ float sFr[128], sFc[128];
    const int tid = threadIdx.x, w = tid >> 5, lane = tid & 31;
    const int wm = w >> 2, wn = w & 3, g = lane >> 2, t4 = lane & 3;
    float acc[4][4][4] = {};

    if (t < 32) {
        const int m0 = (t >> 1) * 128, n0 = (t & 1) * 128;
        gemm_loop<1>(sb, X2h + bz * S_LH, HDIM, m0, W2h + bz * S_DH, HDIM, n0,
                     0, HDIM, acc, tid, lane, wm, wn);
        const __half* Vh = qkvh + bz * S_L3D + 2 * DDIM;
        __half* C = gZ2h + bz * S_LD;
#pragma unroll
        for (int mi = 0; mi < 4; mi++)
#pragma unroll
        for (int hf = 0; hf < 2; hf++) {
            const int r = m0 + wm * 64 + mi * 16 + g + hf * 8;
#pragma unroll
            for (int ni = 0; ni < 4; ni++) {
                const int cc = n0 + wn * 32 + ni * 8 + t4 * 2;
                __half2 a2 = *(const __half2*)&Vh[(long)r * L3D + cc];
                *(__half2*)&C[(long)r * DDIM + cc] = __floats2half2_rn(
                    acc[mi][ni][hf * 2]     - __half2float(__low2half(a2)),
                    acc[mi][ni][hf * 2 + 1] - __half2float(__high2half(a2)));
            }
        }
        return;
    }
    const int tt = t - 32;
    const int mm = (tt < 16) ? tt : tt - 15;
    const int nn = (tt < 16) ? tt : tt - 16;
    const int m0 = mm * 128, n0 = nn * 128;
    gemm_loop<1>(sb, qkvh + bz * S_L3D, L3D, m0, qkvh + bz * S_L3D + DDIM, L3D, n0,
                 0, DDIM, acc, tid, lane, wm, wn);
    s_epilogue(acc, Sh + bz * S_LL, m0, n0,
               lrv + (long)bz * LSEQ, LcD + (long)bz * LSEQ, sFr, sFc, tid, lane, wm, wn);
}

// ---------------- attn1 (fused cross+band) + W1/W2-next partials merged ----------------
__global__ void __launch_bounds__(256, 2) attn1wp_k(
    const __half* __restrict__ qkvh, const __half* __restrict__ W1h,
    const __half* __restrict__ Sh, const __half* __restrict__ gZ1h,
    __half* __restrict__ X2nh, const float* __restrict__ cexp,
    const __half* __restrict__ gZ2h, const __half* __restrict__ X2h,
    float* __restrict__ Wsp1, float* __restrict__ Wsp2,
    const float* __restrict__ wfac)
{
    extern __shared__ __align__(16) char dynsm[];
    const uint32_t sb = smem_u32(dynsm);
    const int tid = threadIdx.x, w = tid >> 5, lane = tid & 31;
    const int wm = w >> 2, wn = w & 3, g = lane >> 2, t4 = lane & 3;
    float acc[4][4][4] = {};
    const int x = blockIdx.x;

    if (x < 256) {
        const int bz = x >> 6, rem = x & 63;
        const int m0 = (rem >> 2) * 128, n0 = (rem & 3) * 128;
        const __half* Q = qkvh + bz * S_L3D;
        const float* ce = cexp + (long)bz * LSEQ;
        if (ce[m0] >= CSKIP_TH) {
            gemm_loop<1>(sb, Q, L3D, m0, W1h + bz * S_HD, DDIM, n0,
                         0, DDIM, acc, tid, lane, wm, wn);
#pragma unroll
            for (int mi = 0; mi < 4; mi++)
#pragma unroll
            for (int hf = 0; hf < 2; hf++) {
                const float s = ce[m0 + wm * 64 + mi * 16 + g + hf * 8];
#pragma unroll
                for (int ni = 0; ni < 4; ni++) {
                    acc[mi][ni][hf * 2 + 0] *= s;
                    acc[mi][ni][hf * 2 + 1] *= s;
                }
            }
            cp_wait0(); __syncthreads();
        }
        const int kbeg = (m0 >= 128) ? m0 - BANDBACK : 0;
        gemm_loop<0>(sb, Sh + bz * S_LL, LSEQ, m0, gZ1h + bz * S_LH, HDIM, n0,
                     kbeg, m0 + 128, acc, tid, lane, wm, wn);
        __half* C = X2nh + bz * S_LH;
#pragma unroll
        for (int mi = 0; mi < 4; mi++)
#pragma unroll
        for (int hf = 0; hf < 2; hf++) {
            const int r = m0 + wm * 64 + mi * 16 + g + hf * 8;
#pragma unroll
            for (int ni = 0; ni < 4; ni++) {
                const int cc = n0 + wn * 32 + ni * 8 + t4 * 2;
                float v0 = acc[mi][ni][hf * 2], v1 = acc[mi][ni][hf * 2 + 1];
                *(__half2*)&C[(long)r * HDIM + cc] =
                    __floats2half2_rn(v0 * sigf(v0), v1 * sigf(v1));
            }
        }
        return;
    }

    // W-next split-K partials (1 k-tile each, last WBAND=64 rows, NSPLIT=2)
    const int u = x - 256;
    const bool isW2 = (u >= 64);
    const int v = u & 63;
    const int z = v >> 3;
    const int tile = v & 7;
    const int bz = z >> 1, sp = z & 1;
    int m0, n0, lda, ldb, ldc;
    const __half *A, *B; float* C;
    if (!isW2) {
        m0 = (tile >> 1) * 128; n0 = (tile & 1) * 128;
        A = gZ1h + bz * S_LH + (long)(LSEQ - WBAND) * HDIM; lda = HDIM;
        B = qkvh + bz * S_L3D + (long)(LSEQ - WBAND) * L3D + DDIM; ldb = L3D;
        C = Wsp1 + (long)z * S_HD; ldc = DDIM;
    } else {
        m0 = (tile >> 2) * 128; n0 = (tile & 3) * 128;
        A = gZ2h + bz * S_LD + (long)(LSEQ - WBAND) * DDIM; lda = DDIM;
        B = X2h + bz * S_LH + (long)(LSEQ - WBAND) * HDIM; ldb = HDIM;
        C = Wsp2 + (long)z * S_DH; ldc = HDIM;
    }
    const float* wsc = wfac + (long)bz * LSEQ + (LSEQ - WBAND);
    const int k0 = sp * 32;
    st_km_scaled(dynsm, A, lda, m0, k0, wsc, tid);
    ld_kn(sb + 10240, B, ldb, n0, k0, tid);
    cp_commit(); cp_wait0();
    __syncthreads();
    compute_tile<1, 0>(sb, sb + 10240, acc, lane, wm, wn);
#pragma unroll
    for (int mi = 0; mi < 4; mi++)
#pragma unroll
    for (int hf = 0; hf < 2; hf++) {
        const int r = m0 + wm * 64 + mi * 16 + g + hf * 8;
#pragma unroll
        for (int ni = 0; ni < 4; ni++) {
            const int cc = n0 + wn * 32 + ni * 8 + t4 * 2;
            *(float2*)&C[(long)r * ldc + cc] =
                make_float2(acc[mi][ni][hf * 2], acc[mi][ni][hf * 2 + 1]);
        }
    }
}

// ---------------- S2-gen ----------------
__global__ void __launch_bounds__(256, 2) s2_k(
    const __half* __restrict__ X2nh, const __half* __restrict__ X2h,
    __half* __restrict__ Sh, const float* __restrict__ lrv,
    const double* __restrict__ LcD)
{
    const int t = blockIdx.x;
    const int bz = t / 31, tt = t - bz * 31;
    const int mm = (tt < 16) ? tt : tt - 15;
    const int nn = (tt < 16) ? tt : tt - 16;
    const int m0 = mm * 128, n0 = nn * 128;

    extern __shared__ __align__(16) char dynsm[];
    const uint32_t sb = smem_u32(dynsm);
    __shared__ float sFr[128], sFc[128];
    const int tid = threadIdx.x, w = tid >> 5, lane = tid & 31;
    const int wm = w >> 2, wn = w & 3;
    float acc[4][4][4] = {};

    gemm_loop<1>(sb, X2nh + bz * S_LH, HDIM, m0, X2h + bz * S_LH, HDIM, n0,
                 0, HDIM, acc, tid, lane, wm, wn);
    s_epilogue(acc, Sh + (long)bz * S_LL, m0, n0,
               lrv + (long)bz * LSEQ, LcD + (long)bz * LSEQ, sFr, sFc, tid, lane, wm, wn);
}

// ---------------- attn2 (-> output, first) + W-reduce (filler) merged ----------------
__global__ void __launch_bounds__(256, 2) attnred_k(
    const __half* __restrict__ X2nh, const __half* __restrict__ W2h,
    const __half* __restrict__ Sh, const __half* __restrict__ gZ2h,
    float* __restrict__ Z2o, const float* __restrict__ cexp,
    const float* __restrict__ Wsp1, const float* __restrict__ W1,
    const float* __restrict__ Wsp2, const float* __restrict__ W2,
    const float* __restrict__ clast,
    float* __restrict__ W1o, float* __restrict__ W2o)
{
    const int x = blockIdx.x;
    const int tid = threadIdx.x;

    if (x >= 128) {
        const int u = x - 128;
        const int sel = u >> 9, rem = u & 511;
        const int b = rem >> 7, blk = rem & 127;
        const float *P = sel ? Wsp2 : Wsp1, *W = sel ? W2 : W1;
        float* out = sel ? W2o : W1o;
        const long MN = S_HD;
        const int idx = blk * 256 + tid;
        const float4* Pb = (const float4*)(P + (long)b * NSPLIT * MN);
        float4 s = make_float4(0.f, 0.f, 0.f, 0.f);
#pragma unroll
        for (int sp = 0; sp < NSPLIT; sp++) {
            float4 v = Pb[(long)sp * (MN >> 2) + idx];
            s.x += v.x; s.y += v.y; s.z += v.z; s.w += v.w;
        }
        const float c = clast[b];
        float4 wv = ((const float4*)(W + (long)b * MN))[idx];
        ((float4*)(out + (long)b * MN))[idx] =
            make_float4(c * wv.x - s.x, c * wv.y - s.y, c * wv.z - s.z, c * wv.w - s.w);
        return;
    }

    const int bz = x >> 5, rem = x & 31;
    const int m0 = (rem >> 1) * 128, n0 = (rem & 1) * 128;
    extern __shared__ __align__(16) char dynsm[];
    const uint32_t sb = smem_u32(dynsm);
    const int w = tid >> 5, lane = tid & 31;
    const int wm = w >> 2, wn = w & 3, g = lane >> 2, t4 = lane & 3;
    float acc[4][4][4] = {};
    const float* ce = cexp + (long)bz * LSEQ;

    if (ce[m0] >= CSKIP_TH) {
        gemm_loop<1>(sb, X2nh + bz * S_LH, HDIM, m0, W2h + bz * S_DH, HDIM, n0,
                     0, HDIM, acc, tid, lane, wm, wn);
#pragma unroll
        for (int mi = 0; mi < 4; mi++)
#pragma unroll
        for (int hf = 0; hf < 2; hf++) {
            const float s = ce[m0 + wm * 64 + mi * 16 + g + hf * 8];
#pragma unroll
            for (int ni = 0; ni < 4; ni++) {
                acc[mi][ni][hf * 2 + 0] *= s;
                acc[mi][ni][hf * 2 + 1] *= s;
            }
        }
        cp_wait0(); __syncthreads();
    }
    const int kbeg = (m0 >= 128) ? m0 - BANDBACK : 0;
    gemm_loop<0>(sb, Sh + (long)bz * S_LL, LSEQ, m0, gZ2h + bz * S_LD, DDIM, n0,
                 kbeg, m0 + 128, acc, tid, lane, wm, wn);
    float* C = Z2o + bz * S_LD;
#pragma unroll
    for (int mi = 0; mi < 4; mi++)
#pragma unroll
    for (int hf = 0; hf < 2; hf++) {
        const int r = m0 + wm * 64 + mi * 16 + g + hf * 8;
#pragma unroll
        for (int ni = 0; ni < 4; ni++) {
            const int cc = n0 + wn * 32 + ni * 8 + t4 * 2;
            *(float2*)&C[(long)r * DDIM + cc] =
                make_float2(acc[mi][ni][hf * 2], acc[mi][ni][hf * 2 + 1]);
        }
    }
}

// ---------------- single merged prep ----------------
#define CN1 ((long)BATCH*LSEQ*DDIM)
#define CN2 (CN1 + (long)BATCH*HDIM*DDIM)
#define CN3 (CN2 + (long)BATCH*DDIM*HDIM)
#define PB_CONV ((int)(CN3 / 1024))
#define PB_ROW  (PB_CONV + 1024)
#define PB_T1   (PB_ROW + 192)
#define PB_T2   (PB_T1 + 512)
#define PB_ALL  (PB_T2 + 1)
__global__ void prep_k(const float* __restrict__ x,  __half* __restrict__ xh,
                       const float* __restrict__ W1, __half* __restrict__ W1h,
                       const float* __restrict__ W2, __half* __restrict__ W2h,
                       const float* __restrict__ wlr, const float* __restrict__ wwd,
                       const float* __restrict__ blr, const float* __restrict__ bwd,
                       float* __restrict__ lrraw, float* __restrict__ wdraw,
                       const float* __restrict__ Wq, const float* __restrict__ Wk,
                       const float* __restrict__ Wv, __half* __restrict__ WqkvT,
                       __half* __restrict__ W2Th,
                       const float* __restrict__ bq, const float* __restrict__ bk,
                       const float* __restrict__ bv, float* __restrict__ bqkv)
{
    const int bx = blockIdx.x, tid = threadIdx.x;
    if (bx < PB_CONV) {
        const long e = (long)(bx * 256 + tid) * 4;
        const float* src; __half* dst; long off;
        if (e < CN1)      { src = x;  dst = xh;  off = e; }
        else if (e < CN2) { src = W1; dst = W1h; off = e - CN1; }
        else              { src = W2; dst = W2h; off = e - CN2; }
        float4 v = *(const float4*)(src + off);
        *(__half2*)(dst + off)     = __floats2half2_rn(v.x, v.y);
        *(__half2*)(dst + off + 2) = __floats2half2_rn(v.z, v.w);
        return;
    }
    if (bx < PB_ROW) {
        const int row = (bx - PB_CONV) * 8 + (tid >> 5);
        const int lane = tid & 31;
        const float* xr = x + (long)row * DDIM;
        float s1 = 0.f, s2 = 0.f;
#pragma unroll
        for (int i = lane; i < DDIM; i += 32) {
            float xv = xr[i];
            s1 += xv * wlr[i];
            s2 += xv * wwd[i];
        }
#pragma unroll
        for (int o = 16; o; o >>= 1) {
            s1 += __shfl_xor_sync(0xffffffffu, s1, o);
            s2 += __shfl_xor_sync(0xffffffffu, s2, o);
        }
        if (!lane) { lrraw[row] = s1 + blr[0]; wdraw[row] = s2 + bwd[0]; }
        return;
    }
    __shared__ float tb[32][33];
    const int tx = tid & 31, ty = tid >> 5;
    if (bx < PB_T1) {
        const int u = bx - PB_ROW;
        const int z = u >> 6, b = u & 63;
        const int c0 = (b & 7) * 32, r0 = (b >> 3) * 32;
        const float* in = (z == 0) ? Wq : (z == 1) ? Wk : Wv;
        __half* out = WqkvT + (long)z * DDIM * DDIM;
#pragma unroll
        for (int k = 0; k < 4; k++)
            tb[ty + k * 8][tx] = in[(long)(r0 + ty + k * 8) * DDIM + c0 + tx];
        __syncthreads();
#pragma unroll
        for (int k = 0; k < 4; k++)
            out[(long)(c0 + ty + k * 8) * DDIM + r0 + tx] = __float2half_rn(tb[tx][ty + k * 8]);
        return;
    }
    if (bx < PB_T2) {
        const int u = bx - PB_T1;
        const int b = u >> 7, v = u & 127;
        const int c0 = (v & 15) * 32, r0 = (v >> 4) * 32;
        const float* in = W2 + (long)b * S_DH;
        __half* out = W2Th + (long)b * S_HD;
#pragma unroll
        for (int k = 0; k < 4; k++)
            tb[ty + k * 8][tx] = in[(long)(r0 + ty + k * 8) * HDIM + c0 + tx];
        __syncthreads();
#pragma unroll
        for (int k = 0; k < 4; k++)
            out[(long)(c0 + ty + k * 8) * DDIM + r0 + tx] = __float2half_rn(tb[tx][ty + k * 8]);
        return;
    }
    for (int j = tid; j < 768; j += 256)
        bqkv[j] = (j < 256) ? bq[j] : (j < 512) ? bk[j - 256] : bv[j - 512];
}

// ---------------- launch ----------------
extern "C" void kernel_launch(void* const* d_in, const int* in_sizes, int n_in,
                              void* d_out, int out_size)
{
    const float* x   = (const float*)d_in[0];
    const float* W1  = (const float*)d_in[1];
    const float* W2  = (const float*)d_in[2];
    const float* Wq  = (const float*)d_in[3];
    const float* bq  = (const float*)d_in[4];
    const float* Wk  = (const float*)d_in[5];
    const float* bk  = (const float*)d_in[6];
    const float* Wv  = (const float*)d_in[7];
    const float* bv  = (const float*)d_in[8];
    const float* wlr = (const float*)d_in[9];
    const float* blr = (const float*)d_in[10];
    const float* wwd = (const float*)d_in[11];
    const float* bwd = (const float*)d_in[12];
    const float* lbl = (const float*)d_in[13];
    const float* lbw = (const float*)d_in[14];

    float* Z2o = (float*)d_out;
    float* W1o = Z2o + (long)BATCH * LSEQ * DDIM;
    float* W2o = W1o + (long)BATCH * HDIM * DDIM;

    __half *xh, *WqkvT, *W1h, *W2h, *W2Th, *qkvh, *Z1h, *X2h, *gZ2h, *gZ1h, *X2nh, *Sh;
    float *bqkv, *Wsp1, *Wsp2;
    float *lrv, *cexp, *wfac, *clast, *lrraw, *wdraw;
    double* LcD;
    cudaGetSymbolAddress((void**)&xh,    g_xh);
    cudaGetSymbolAddress((void**)&WqkvT, g_WqkvT);
    cudaGetSymbolAddress((void**)&bqkv,  g_bqkv);
    cudaGetSymbolAddress((void**)&W1h,   g_W1h);
    cudaGetSymbolAddress((void**)&W2h,   g_W2h);
    cudaGetSymbolAddress((void**)&W2Th,  g_W2Th);
    cudaGetSymbolAddress((void**)&qkvh,  g_qkvh);
    cudaGetSymbolAddress((void**)&Z1h,   g_Z1h);
    cudaGetSymbolAddress((void**)&X2h,   g_X2h);
    cudaGetSymbolAddress((void**)&gZ2h,  g_gZ2h);
    cudaGetSymbolAddress((void**)&gZ1h,  g_gZ1h);
    cudaGetSymbolAddress((void**)&X2nh,  g_X2nh);
    cudaGetSymbolAddress((void**)&Sh,    g_Sh);
    cudaGetSymbolAddress((void**)&Wsp1,  g_Wsp1);
    cudaGetSymbolAddress((void**)&Wsp2,  g_Wsp2);
    cudaGetSymbolAddress((void**)&lrv,   g_lr);
    cudaGetSymbolAddress((void**)&LcD,   g_LcD);
    cudaGetSymbolAddress((void**)&cexp,  g_cexp);
    cudaGetSymbolAddress((void**)&wfac,  g_wfac);
    cudaGetSymbolAddress((void**)&clast, g_clast);
    cudaGetSymbolAddress((void**)&lrraw, g_lrraw);
    cudaGetSymbolAddress((void**)&wdraw, g_wdraw);

    cudaFuncSetAttribute(qkvscan_k,          cudaFuncAttributeMaxDynamicSharedMemorySize, SMEM_DYN);
    cudaFuncSetAttribute(hgemm_k<EPI_SILU2>, cudaFuncAttributeMaxDynamicSharedMemorySize, SMEM_DYN);
    cudaFuncSetAttribute(hgemm_k<EPI_G1>,    cudaFuncAttributeMaxDynamicSharedMemorySize, SMEM_DYN);
    cudaFuncSetAttribute(gzs1_k,             cudaFuncAttributeMaxDynamicSharedMemorySize, SMEM_DYN);
    cudaFuncSetAttribute(attn1wp_k,          cudaFuncAttributeMaxDynamicSharedMemorySize, SMEM_DYN);
    cudaFuncSetAttribute(s2_k,               cudaFuncAttributeMaxDynamicSharedMemorySize, SMEM_DYN);
    cudaFuncSetAttribute(attnred_k,          cudaFuncAttributeMaxDynamicSharedMemorySize, SMEM_DYN);

    dim3 blk(256);

    // 1: ALL prep
    prep_k<<<PB_ALL, 256>>>(x, xh, W1, W1h, W2, W2h, wlr, wwd, blr, bwd, lrraw, wdraw,
                            Wq, Wk, Wv, WqkvT, W2Th, bq, bk, bv, bqkv);

    // 2: QKV (all-half) + scan
    qkvscan_k<<<dim3(7, 16, BATCH), blk, SMEM_DYN>>>(
        xh, WqkvT, qkvh, bqkv,
        lrraw, wdraw, lbl, lbw, lrv, LcD, cexp, wfac, clast);

    // 3: Z1 (half) + X2 = silu(Z1)
    hgemm_k<EPI_SILU2><<<dim3(4, 16, BATCH), blk, SMEM_DYN>>>(
        qkvh + DDIM, S_L3D, L3D,  W1h, S_HD, DDIM,  Z1h, S_LH, HDIM,  DDIM,
        nullptr, 0, 0,  X2h, S_LH);

    // 4: gZ2 + S1-gen (merged; V read as half from qkvh)
    gzs1_k<<<dim3(63, 1, BATCH), blk, SMEM_DYN>>>(
        X2h, W2h, qkvh, gZ2h, Sh, lrv, LcD);

    // 5: gZ1 = silu'(Z1) * (gZ2 @ W2)
    hgemm_k<EPI_G1><<<dim3(4, 16, BATCH), blk, SMEM_DYN>>>(
        gZ2h, S_LD, DDIM,  W2Th, S_HD, DDIM,  gZ1h, S_LH, HDIM,  DDIM,
        Z1h, S_LH, HDIM,  nullptr, 0);

    // 6: attn1 (fused, band 64) + W-next partials
    attn1wp_k<<<dim3(384, 1, 1), blk, SMEM_DYN>>>(
        qkvh, W1h, Sh, gZ1h, X2nh, cexp, gZ2h, X2h, Wsp1, Wsp2, wfac);

    // 7: S2-gen
    s2_k<<<dim3(124, 1, 1), blk, SMEM_DYN>>>(X2nh, X2h, Sh, lrv, LcD);

    // 8: attn2 (band 64) -> output + W-reduce filler
    attnred_k<<<dim3(128 + 1024, 1, 1), blk, SMEM_DYN>>>(
        X2nh, W2h, Sh, gZ2h, Z2o, cexp, Wsp1, W1, Wsp2, W2, clast, W1o, W2o);
}